// round 9
// baseline (speedup 1.0000x reference)
#include <cuda_runtime.h>
#include <cuda_bf16.h>
#include <cstdint>

#define BB   8
#define NPTS 2048
#define KNN  10
#define MAXF 1024
#define SLOPE 0.2f
#define KPMAX 1536
#define SMPAD 40
#define NTILES 16
#define NPAIRS 136   // NTILES*(NTILES+1)/2

// ---------------- static scratch ----------------
__device__ float g_feat_a[BB * NPTS * MAXF];
__device__ float g_feat_b[BB * NPTS * MAXF];
__device__ float g_center[BB * NPTS * MAXF];
__device__ float g_y[(size_t)BB * NPTS * MAXF];
__device__ __align__(16) __nv_bfloat16 g_xa[(size_t)BB * NPTS * KPMAX];  // (h,l,h)
__device__ __align__(16) __nv_bfloat16 g_xb[(size_t)BB * NPTS * KPMAX];  // (h,h,l)
__device__ __align__(16) __nv_bfloat16 g_w1t[1024 * KPMAX];
__device__ __align__(16) __nv_bfloat16 g_w2t[1024 * KPMAX];
__device__ float g_cd2[(size_t)BB * NPTS * NTILES * KNN];
__device__ int   g_cidx[(size_t)BB * NPTS * NTILES * KNN];
__device__ float g_sq[BB * NPTS];
__device__ int   g_idx[BB * NPTS * KNN];
__device__ float g_pool[BB * MAXF];
__device__ float g_m1[BB * 128];
__device__ float g_m2[BB * 64];

// ---------------- conversions: fp32 -> 3-slot bf16 split ----------------
__global__ void convert_x(const float* __restrict__ X, __nv_bfloat16* __restrict__ Xa,
                          __nv_bfloat16* __restrict__ Xb, int fin, int Kp, int M) {
    int idx = blockIdx.x * blockDim.x + threadIdx.x;
    if (idx >= M * Kp) return;
    int r = idx / Kp, c = idx % Kp;
    __nv_bfloat16 va = __float2bfloat16(0.f), vb = va;
    if (c < 3 * fin) {
        int s = c / fin, cc = c - s * fin;
        float v = X[(size_t)r * fin + cc];
        __nv_bfloat16 h = __float2bfloat16(v);
        __nv_bfloat16 l = __float2bfloat16(v - __bfloat162float(h));
        va = (s == 1) ? l : h;
        vb = (s == 2) ? l : h;
    }
    Xa[(size_t)r * Kp + c] = va;
    Xb[(size_t)r * Kp + c] = vb;
}

__global__ void convert_w(const float* __restrict__ W, __nv_bfloat16* __restrict__ Wt,
                          int fin, int fout, int Kp) {
    int idx = blockIdx.x * blockDim.x + threadIdx.x;
    if (idx >= fout * Kp) return;
    int n = idx / Kp, c = idx % Kp;
    __nv_bfloat16 o = __float2bfloat16(0.f);
    if (c < 3 * fin) {
        int s = c / fin, cc = c - s * fin;
        float v = W[(size_t)cc * fout + n];
        __nv_bfloat16 h = __float2bfloat16(v);
        o = (s == 2) ? __float2bfloat16(v - __bfloat162float(h)) : h;
    }
    Wt[(size_t)n * Kp + c] = o;
}

// ---------------- MMA primitives (round-7, verified) ----------------
#define MMA_BF16(c, a, b)                                                          \
    asm volatile("mma.sync.aligned.m16n8k16.row.col.f32.bf16.bf16.f32 "            \
                 "{%0,%1,%2,%3}, {%4,%5,%6,%7}, {%8,%9}, {%0,%1,%2,%3};"           \
                 : "+f"(c[0]), "+f"(c[1]), "+f"(c[2]), "+f"(c[3])                  \
                 : "r"(a[0]), "r"(a[1]), "r"(a[2]), "r"(a[3]), "r"(b[0]), "r"(b[1]))

__device__ __forceinline__ void cpa16(void* smem, const void* gmem) {
    uint32_t s = (uint32_t)__cvta_generic_to_shared(smem);
    asm volatile("cp.async.ca.shared.global [%0], [%1], 16;" :: "r"(s), "l"(gmem));
}
__device__ __forceinline__ void ldsm_x4(uint32_t* r, const void* p) {
    uint32_t a = (uint32_t)__cvta_generic_to_shared(p);
    asm volatile("ldmatrix.sync.aligned.m8n8.x4.shared.b16 {%0,%1,%2,%3}, [%4];"
                 : "=r"(r[0]), "=r"(r[1]), "=r"(r[2]), "=r"(r[3]) : "r"(a));
}
__device__ __forceinline__ void ldsm_x2(uint32_t* r, const void* p) {
    uint32_t a = (uint32_t)__cvta_generic_to_shared(p);
    asm volatile("ldmatrix.sync.aligned.m8n8.x2.shared.b16 {%0,%1}, [%2];"
                 : "=r"(r[0]), "=r"(r[1]) : "r"(a));
}

__device__ __forceinline__ void stage_load(__nv_bfloat16 (*S)[SMPAD],
                                           const __nv_bfloat16* __restrict__ src,
                                           int row0, int Kp, int k0, int tid) {
#pragma unroll
    for (int it = 0; it < 2; it++) {
        int e = tid + it * 256;
        int r = e >> 2;
        int cb = (e & 3) * 8;
        cpa16(&S[r][cb], src + (size_t)(row0 + r) * Kp + k0 + cb);
    }
}

__device__ __forceinline__ void stage_mma(const __nv_bfloat16 (*As)[SMPAD],
                                          const __nv_bfloat16 (*Bs)[SMPAD],
                                          float acc[4][4][4], int wm, int wn, int lane) {
    int a_row = (lane & 15);
    int a_col = (lane >> 4) * 8;
    int b_row = (lane & 7);
    int b_col = ((lane >> 3) & 1) * 8;
#pragma unroll
    for (int ks = 0; ks < 2; ks++) {
        int kb = ks * 16;
        uint32_t ar[4][4], br[4][2];
#pragma unroll
        for (int mi = 0; mi < 4; mi++)
            ldsm_x4(ar[mi], &As[wm + mi * 16 + a_row][kb + a_col]);
#pragma unroll
        for (int ni = 0; ni < 4; ni++)
            ldsm_x2(br[ni], &Bs[wn + ni * 8 + b_row][kb + b_col]);
#pragma unroll
        for (int mi = 0; mi < 4; mi++)
#pragma unroll
            for (int ni = 0; ni < 4; ni++) MMA_BF16(acc[mi][ni], ar[mi], br[ni]);
    }
}

__device__ __forceinline__ bool dless(float a, int ia, float bv, int ib) {
    return (a < bv) || (a == bv && ia < ib);
}

__device__ __forceinline__ void tk_insert(float d2, int j, float* best, int* bidx) {
    if (dless(d2, j, best[KNN - 1], bidx[KNN - 1])) {
        int m = KNN - 1;
#pragma unroll
        for (int tt = KNN - 1; tt > 0; tt--) {
            if (m == tt && dless(d2, j, best[tt - 1], bidx[tt - 1])) {
                best[tt] = best[tt - 1]; bidx[tt] = bidx[tt - 1]; m = tt - 1;
            }
        }
        best[m] = d2; bidx[m] = j;
    }
}

// ---------------- NN: C[M,Nn] = Xa @ Wt^T (+bias)  (round-7 verbatim) ----------------
__global__ __launch_bounds__(256) void mma_nn(const __nv_bfloat16* __restrict__ A,
                                              const __nv_bfloat16* __restrict__ B,
                                              const float* __restrict__ bias,
                                              float* __restrict__ C,
                                              int Kp, int Nn) {
    __shared__ __align__(16) __nv_bfloat16 As[2][128][SMPAD];
    __shared__ __align__(16) __nv_bfloat16 Bs[2][128][SMPAD];
    int tid = threadIdx.x;
    int m0 = blockIdx.y * 128, o0 = blockIdx.x * 128;
    int lane = tid & 31, warp = tid >> 5;
    int wm = (warp & 1) * 64, wn = (warp >> 1) * 32;
    int nk = Kp / 32;

    float acc[4][4][4];
#pragma unroll
    for (int mi = 0; mi < 4; mi++)
#pragma unroll
        for (int ni = 0; ni < 4; ni++)
#pragma unroll
            for (int c = 0; c < 4; c++) acc[mi][ni][c] = 0.f;

    stage_load(As[0], A, m0, Kp, 0, tid);
    stage_load(Bs[0], B, o0, Kp, 0, tid);
    asm volatile("cp.async.commit_group;");

    for (int kt = 0; kt < nk; kt++) {
        if (kt + 1 < nk) {
            stage_load(As[(kt + 1) & 1], A, m0, Kp, (kt + 1) * 32, tid);
            stage_load(Bs[(kt + 1) & 1], B, o0, Kp, (kt + 1) * 32, tid);
            asm volatile("cp.async.commit_group;");
            asm volatile("cp.async.wait_group 1;");
        } else {
            asm volatile("cp.async.wait_group 0;");
        }
        __syncthreads();
        stage_mma(As[kt & 1], Bs[kt & 1], acc, wm, wn, lane);
        __syncthreads();
    }

    int g = lane >> 2, t = lane & 3;
#pragma unroll
    for (int mi = 0; mi < 4; mi++) {
        int row = m0 + wm + mi * 16 + g;
#pragma unroll
        for (int ni = 0; ni < 4; ni++) {
            int col = o0 + wn + ni * 8 + 2 * t;
            if (col < Nn) {
                float b0 = bias ? bias[col] : 0.f;
                float b1 = bias ? bias[col + 1] : 0.f;
                *(float2*)(C + (size_t)row * Nn + col) =
                    make_float2(acc[mi][ni][0] + b0, acc[mi][ni][1] + b1);
                *(float2*)(C + (size_t)(row + 8) * Nn + col) =
                    make_float2(acc[mi][ni][2] + b0, acc[mi][ni][3] + b1);
            }
        }
    }
}

// ---------------- fused symmetric NT + per-tile top-K ----------------
// One block per (upper-triangle tile pair, batch). 2-stage static pipeline;
// stage smem reused as 32x133 fp32 scratch for chunked scans.
__global__ __launch_bounds__(256) void mma_nt_topk(const __nv_bfloat16* __restrict__ Xa,
                                                   const __nv_bfloat16* __restrict__ Xb,
                                                   float* __restrict__ cd2,
                                                   int* __restrict__ cidx, int Kp) {
    __shared__ __align__(16) __nv_bfloat16 As[2][128][SMPAD];
    __shared__ __align__(16) __nv_bfloat16 Bs[2][128][SMPAD];
    __shared__ float sqm[128], sqn[128];

    int b = blockIdx.z;
    // decode upper-triangle pair (ti <= tj)
    int p = blockIdx.x;
    int ti = 0;
    while (p >= NTILES - ti) { p -= NTILES - ti; ti++; }
    int tj = ti + p;
    int m0 = ti * 128, n0 = tj * 128;

    const __nv_bfloat16* Ab = Xa + (size_t)b * NPTS * Kp;
    const __nv_bfloat16* Bb = Xb + (size_t)b * NPTS * Kp;
    int tid = threadIdx.x;
    int lane = tid & 31, warp = tid >> 5;
    int wm = (warp & 1) * 64, wn = (warp >> 1) * 32;
    int nk = Kp / 32;

    if (tid < 128) {
        sqm[tid] = g_sq[b * NPTS + m0 + tid];
        sqn[tid] = g_sq[b * NPTS + n0 + tid];
    }

    float acc[4][4][4];
#pragma unroll
    for (int mi = 0; mi < 4; mi++)
#pragma unroll
        for (int ni = 0; ni < 4; ni++)
#pragma unroll
            for (int c = 0; c < 4; c++) acc[mi][ni][c] = 0.f;

    stage_load(As[0], Ab, m0, Kp, 0, tid);
    stage_load(Bs[0], Bb, n0, Kp, 0, tid);
    asm volatile("cp.async.commit_group;");

    for (int kt = 0; kt < nk; kt++) {
        if (kt + 1 < nk) {
            stage_load(As[(kt + 1) & 1], Ab, m0, Kp, (kt + 1) * 32, tid);
            stage_load(Bs[(kt + 1) & 1], Bb, n0, Kp, (kt + 1) * 32, tid);
            asm volatile("cp.async.commit_group;");
            asm volatile("cp.async.wait_group 1;");
        } else {
            asm volatile("cp.async.wait_group 0;");
        }
        __syncthreads();
        stage_mma(As[kt & 1], Bs[kt & 1], acc, wm, wn, lane);
        __syncthreads();
    }

    // reuse pipeline smem as fp32 scratch (17KB <= 20KB of As)
    float (*Sc)[133] = (float(*)[133])(&As[0][0][0]);
    int g = lane >> 2, t = lane & 3;

    // n-side running top-K (column scan), kept across chunks
    float nbest[KNN]; int nbidx[KNN];
#pragma unroll
    for (int m = 0; m < KNN; m++) { nbest[m] = 3.0e38f; nbidx[m] = 0x7fffffff; }

    for (int ch = 0; ch < 4; ch++) {
        int c0 = ch * 32;
        // dump acc rows [c0, c0+32)
#pragma unroll
        for (int mi = 0; mi < 4; mi++) {
            int row = wm + mi * 16 + g;
#pragma unroll
            for (int ni = 0; ni < 4; ni++) {
                int col = wn + ni * 8 + 2 * t;
                if (row >= c0 && row < c0 + 32) {
                    Sc[row - c0][col] = acc[mi][ni][0];
                    Sc[row - c0][col + 1] = acc[mi][ni][1];
                }
                int r2 = row + 8;
                if (r2 >= c0 && r2 < c0 + 32) {
                    Sc[r2 - c0][col] = acc[mi][ni][2];
                    Sc[r2 - c0][col + 1] = acc[mi][ni][3];
                }
            }
        }
        __syncthreads();

        if (tid < 128) {
            // n-side: column tid over 32 rows of this chunk
            float sj = sqn[tid];
            for (int r = 0; r < 32; r++) {
                float d2 = sqm[c0 + r] + sj - 2.0f * Sc[r][tid];
                tk_insert(d2, m0 + c0 + r, nbest, nbidx);
            }
        } else if (tid < 160) {
            // m-side: row r over all 128 cols; per-chunk local top-K
            int r = tid - 128;
            float si = sqm[c0 + r];
            float best[KNN]; int bidx[KNN];
#pragma unroll
            for (int m = 0; m < KNN; m++) { best[m] = 3.0e38f; bidx[m] = 0x7fffffff; }
            for (int c = 0; c < 128; c++) {
                float d2 = si + sqn[c] - 2.0f * Sc[r][c];
                tk_insert(d2, n0 + c, best, bidx);
            }
            size_t base = ((size_t)(b * NPTS + m0 + c0 + r) * NTILES + tj) * KNN;
#pragma unroll
            for (int m = 0; m < KNN; m++) { cd2[base + m] = best[m]; cidx[base + m] = bidx[m]; }
        }
        __syncthreads();
    }

    if (ti != tj && tid < 128) {
        size_t base = ((size_t)(b * NPTS + n0 + tid) * NTILES + ti) * KNN;
#pragma unroll
        for (int m = 0; m < KNN; m++) { cd2[base + m] = nbest[m]; cidx[base + m] = nbidx[m]; }
    }
}

// ---------------- merge per-tile candidates: warp per row (round-8, verified) ----------------
__global__ void topk_merge(const float* __restrict__ cd2, const int* __restrict__ cidx) {
    int gwarp = (blockIdx.x * blockDim.x + threadIdx.x) >> 5;
    int lane = threadIdx.x & 31;
    if (gwarp >= BB * NPTS) return;
    size_t base = (size_t)gwarp * (NTILES * KNN);

    float best[KNN];
    int bidx[KNN];
#pragma unroll
    for (int m = 0; m < KNN; m++) { best[m] = 3.0e38f; bidx[m] = 0x7fffffff; }

    for (int j = lane; j < NTILES * KNN; j += 32)
        tk_insert(cd2[base + j], cidx[base + j], best, bidx);

    int ptr = 0;
    for (int r = 0; r < KNN; r++) {
        float v = (ptr < KNN) ? best[ptr] : 3.0e38f;
        int jj = (ptr < KNN) ? bidx[ptr] : 0x7fffffff;
        float mv = v; int mj = jj;
#pragma unroll
        for (int off = 16; off > 0; off >>= 1) {
            float ov = __shfl_down_sync(0xffffffffu, mv, off);
            int oj = __shfl_down_sync(0xffffffffu, mj, off);
            if (dless(ov, oj, mv, mj)) { mv = ov; mj = oj; }
        }
        mv = __shfl_sync(0xffffffffu, mv, 0);
        mj = __shfl_sync(0xffffffffu, mj, 0);
        if (jj == mj && v == mv) ptr++;
        if (lane == 0) g_idx[(size_t)gwarp * KNN + r] = mj;
    }
}

// ---------------- squared norms ----------------
__global__ void sq_kernel(const float* __restrict__ X, int Kd) {
    int i = blockIdx.x * blockDim.x + threadIdx.x;
    if (i < BB * NPTS) {
        const float* p = X + (size_t)i * Kd;
        float s = 0.f;
        for (int f = 0; f < Kd; f++) s += p[f] * p[f];
        g_sq[i] = s;
    }
}

// ---------------- gather-max edge conv epilogue ----------------
__global__ __launch_bounds__(256) void gathermax_kernel(const float* __restrict__ Z,
                                                        const float* __restrict__ Y,
                                                        const int* __restrict__ idx,
                                                        float* __restrict__ Out,
                                                        int fout) {
    int bn = blockIdx.x;
    int b = bn >> 11;
    const int* ip = idx + (size_t)bn * KNN;
    __shared__ int nb[KNN];
    if (threadIdx.x < KNN) nb[threadIdx.x] = ip[threadIdx.x];
    __syncthreads();

    const float* Yb = Y + (size_t)b * NPTS * fout;
    size_t base = (size_t)bn * fout;

    for (int o = threadIdx.x * 4; o < fout; o += blockDim.x * 4) {
        float4 m = make_float4(-3.0e38f, -3.0e38f, -3.0e38f, -3.0e38f);
#pragma unroll
        for (int k = 0; k < KNN; k++) {
            float4 v = *(const float4*)(Yb + (size_t)nb[k] * fout + o);
            m.x = fmaxf(m.x, v.x);
            m.y = fmaxf(m.y, v.y);
            m.z = fmaxf(m.z, v.z);
            m.w = fmaxf(m.w, v.w);
        }
        float4 z = *(const float4*)(Z + base + o);
        float4 y = *(const float4*)(Y + base + o);
        float4 h;
        h.x = z.x - y.x + m.x;
        h.y = z.y - y.y + m.y;
        h.z = z.z - y.z + m.z;
        h.w = z.w - y.w + m.w;
        h.x = (h.x > 0.f) ? h.x : SLOPE * h.x;
        h.y = (h.y > 0.f) ? h.y : SLOPE * h.y;
        h.z = (h.z > 0.f) ? h.z : SLOPE * h.z;
        h.w = (h.w > 0.f) ? h.w : SLOPE * h.w;
        *(float4*)(Out + base + o) = h;
    }
}

// ---------------- global max pool over N ----------------
__global__ void pool_kernel(const float* __restrict__ H, int Fo) {
    int b = blockIdx.y;
    int o = blockIdx.x * blockDim.x + threadIdx.x;
    if (o < Fo) {
        float m = -3.0e38f;
        for (int n = 0; n < NPTS; n++)
            m = fmaxf(m, H[((size_t)b * NPTS + n) * Fo + o]);
        g_pool[b * Fo + o] = m;
    }
}

// ---------------- small MLP layer ----------------
__global__ void mlp_kernel(const float* __restrict__ A, const float* __restrict__ W,
                           const float* __restrict__ bias, float* __restrict__ C,
                           int M, int Kd, int Nn) {
    for (int i = threadIdx.x; i < M * Nn; i += blockDim.x) {
        int m = i / Nn, o = i % Nn;
        float s = bias[o];
        for (int f = 0; f < Kd; f++) s += A[(size_t)m * Kd + f] * W[(size_t)f * Nn + o];
        C[i] = s;
    }
}

// ---------------- launcher ----------------
extern "C" void kernel_launch(void* const* d_in, const int* in_sizes, int n_in,
                              void* d_out, int out_size) {
    const float* x = (const float*)d_in[0];
    const float* w[5];
    const float* bs[5];
    for (int l = 0; l < 5; l++) {
        w[l] = (const float*)d_in[1 + 2 * l];
        bs[l] = (const float*)d_in[2 + 2 * l];
    }
    const float* m0w = (const float*)d_in[11];
    const float* m0b = (const float*)d_in[12];
    const float* m1w = (const float*)d_in[13];
    const float* m1b = (const float*)d_in[14];
    const float* m2w = (const float*)d_in[15];
    const float* m2b = (const float*)d_in[16];
    float* out = (float*)d_out;

    float *feat_a, *feat_b, *centerp, *yp, *poolp, *m1p, *m2p, *cd2p;
    __nv_bfloat16 *xap, *xbp, *w1tp, *w2tp;
    int *idxp, *cidxp;
    cudaGetSymbolAddress((void**)&feat_a, g_feat_a);
    cudaGetSymbolAddress((void**)&feat_b, g_feat_b);
    cudaGetSymbolAddress((void**)&centerp, g_center);
    cudaGetSymbolAddress((void**)&yp, g_y);
    cudaGetSymbolAddress((void**)&poolp, g_pool);
    cudaGetSymbolAddress((void**)&m1p, g_m1);
    cudaGetSymbolAddress((void**)&m2p, g_m2);
    cudaGetSymbolAddress((void**)&xap, g_xa);
    cudaGetSymbolAddress((void**)&xbp, g_xb);
    cudaGetSymbolAddress((void**)&w1tp, g_w1t);
    cudaGetSymbolAddress((void**)&w2tp, g_w2t);
    cudaGetSymbolAddress((void**)&idxp, g_idx);
    cudaGetSymbolAddress((void**)&cd2p, g_cd2);
    cudaGetSymbolAddress((void**)&cidxp, g_cidx);

    const int fins[5] = {3, 64, 128, 256, 512};
    const int fouts[5] = {64, 128, 256, 512, 1024};
    float* bufs[2] = {feat_a, feat_b};
    const int M = BB * NPTS;

    const float* cur = x;
    for (int l = 0; l < 5; l++) {
        int fin = fins[l], fout = fouts[l];
        int Kp = ((3 * fin + 31) / 32) * 32;
        int gx = (fout + 127) / 128;

        convert_x<<<(M * Kp + 255) / 256, 256>>>(cur, xap, xbp, fin, Kp, M);
        convert_w<<<(fout * Kp + 255) / 256, 256>>>(w[l], w1tp, fin, fout, Kp);
        convert_w<<<(fout * Kp + 255) / 256, 256>>>(w[l] + (size_t)fin * fout, w2tp,
                                                    fin, fout, Kp);
        sq_kernel<<<(M + 255) / 256, 256>>>(cur, fin);

        mma_nt_topk<<<dim3(NPAIRS, 1, BB), 256>>>(xap, xbp, cd2p, cidxp, Kp);
        topk_merge<<<M / 8, 256>>>(cd2p, cidxp);

        mma_nn<<<dim3(gx, M / 128), 256>>>(xap, w1tp, bs[l], centerp, Kp, fout);
        mma_nn<<<dim3(gx, M / 128), 256>>>(xap, w2tp, nullptr, yp, Kp, fout);

        gathermax_kernel<<<M, 256>>>(centerp, yp, idxp, bufs[l & 1], fout);
        cur = bufs[l & 1];
    }

    pool_kernel<<<dim3(MAXF / 256, BB), 256>>>(cur, MAXF);
    mlp_kernel<<<1, 1024>>>(poolp, m0w, m0b, m1p, BB, 1024, 128);
    mlp_kernel<<<1, 512>>>(m1p, m1w, m1b, m2p, BB, 128, 64);
    mlp_kernel<<<1, 256>>>(m2p, m2w, m2b, out, BB, 64, 1);
}

// round 10
// speedup vs baseline: 2.4162x; 2.4162x over previous
#include <cuda_runtime.h>
#include <cuda_bf16.h>
#include <cstdint>

#define BB   8
#define NPTS 2048
#define KNN  10
#define MAXF 1024
#define SLOPE 0.2f
#define KPMAX 1536
#define SMPAD 40
#define NTILES 16
#define NPAIRS 136   // NTILES*(NTILES+1)/2

// ---------------- static scratch ----------------
__device__ float g_feat_a[BB * NPTS * MAXF];
__device__ float g_feat_b[BB * NPTS * MAXF];
__device__ float g_center[BB * NPTS * MAXF];
__device__ float g_dot[(size_t)BB * NPTS * NPTS];   // reused as Y after topk
__device__ __align__(16) __nv_bfloat16 g_xa[(size_t)BB * NPTS * KPMAX];  // (h,l,h)
__device__ __align__(16) __nv_bfloat16 g_xb[(size_t)BB * NPTS * KPMAX];  // (h,h,l)
__device__ __align__(16) __nv_bfloat16 g_w1t[1024 * KPMAX];
__device__ __align__(16) __nv_bfloat16 g_w2t[1024 * KPMAX];
__device__ float g_sq[BB * NPTS];
__device__ int   g_idx[BB * NPTS * KNN];
__device__ float g_pool[BB * MAXF];
__device__ float g_m1[BB * 128];
__device__ float g_m2[BB * 64];

// ---------------- conversions: fp32 -> 3-slot bf16 split ----------------
__global__ void convert_x(const float* __restrict__ X, __nv_bfloat16* __restrict__ Xa,
                          __nv_bfloat16* __restrict__ Xb, int fin, int Kp, int M) {
    int idx = blockIdx.x * blockDim.x + threadIdx.x;
    if (idx >= M * Kp) return;
    int r = idx / Kp, c = idx % Kp;
    __nv_bfloat16 va = __float2bfloat16(0.f), vb = va;
    if (c < 3 * fin) {
        int s = c / fin, cc = c - s * fin;
        float v = X[(size_t)r * fin + cc];
        __nv_bfloat16 h = __float2bfloat16(v);
        __nv_bfloat16 l = __float2bfloat16(v - __bfloat162float(h));
        va = (s == 1) ? l : h;
        vb = (s == 2) ? l : h;
    }
    Xa[(size_t)r * Kp + c] = va;
    Xb[(size_t)r * Kp + c] = vb;
}

__global__ void convert_w(const float* __restrict__ W, __nv_bfloat16* __restrict__ Wt,
                          int fin, int fout, int Kp) {
    int idx = blockIdx.x * blockDim.x + threadIdx.x;
    if (idx >= fout * Kp) return;
    int n = idx / Kp, c = idx % Kp;
    __nv_bfloat16 o = __float2bfloat16(0.f);
    if (c < 3 * fin) {
        int s = c / fin, cc = c - s * fin;
        float v = W[(size_t)cc * fout + n];
        __nv_bfloat16 h = __float2bfloat16(v);
        o = (s == 2) ? __float2bfloat16(v - __bfloat162float(h)) : h;
    }
    Wt[(size_t)n * Kp + c] = o;
}

// ---------------- MMA primitives (round-7, verified) ----------------
#define MMA_BF16(c, a, b)                                                          \
    asm volatile("mma.sync.aligned.m16n8k16.row.col.f32.bf16.bf16.f32 "            \
                 "{%0,%1,%2,%3}, {%4,%5,%6,%7}, {%8,%9}, {%0,%1,%2,%3};"           \
                 : "+f"(c[0]), "+f"(c[1]), "+f"(c[2]), "+f"(c[3])                  \
                 : "r"(a[0]), "r"(a[1]), "r"(a[2]), "r"(a[3]), "r"(b[0]), "r"(b[1]))

__device__ __forceinline__ void cpa16(void* smem, const void* gmem) {
    uint32_t s = (uint32_t)__cvta_generic_to_shared(smem);
    asm volatile("cp.async.ca.shared.global [%0], [%1], 16;" :: "r"(s), "l"(gmem));
}
__device__ __forceinline__ void ldsm_x4(uint32_t* r, const void* p) {
    uint32_t a = (uint32_t)__cvta_generic_to_shared(p);
    asm volatile("ldmatrix.sync.aligned.m8n8.x4.shared.b16 {%0,%1,%2,%3}, [%4];"
                 : "=r"(r[0]), "=r"(r[1]), "=r"(r[2]), "=r"(r[3]) : "r"(a));
}
__device__ __forceinline__ void ldsm_x2(uint32_t* r, const void* p) {
    uint32_t a = (uint32_t)__cvta_generic_to_shared(p);
    asm volatile("ldmatrix.sync.aligned.m8n8.x2.shared.b16 {%0,%1}, [%2];"
                 : "=r"(r[0]), "=r"(r[1]) : "r"(a));
}

__device__ __forceinline__ void stage_load(__nv_bfloat16 (*S)[SMPAD],
                                           const __nv_bfloat16* __restrict__ src,
                                           int row0, int Kp, int k0, int tid) {
#pragma unroll
    for (int it = 0; it < 2; it++) {
        int e = tid + it * 256;
        int r = e >> 2;
        int cb = (e & 3) * 8;
        cpa16(&S[r][cb], src + (size_t)(row0 + r) * Kp + k0 + cb);
    }
}

__device__ __forceinline__ void stage_mma(const __nv_bfloat16 (*As)[SMPAD],
                                          const __nv_bfloat16 (*Bs)[SMPAD],
                                          float acc[4][4][4], int wm, int wn, int lane) {
    int a_row = (lane & 15);
    int a_col = (lane >> 4) * 8;
    int b_row = (lane & 7);
    int b_col = ((lane >> 3) & 1) * 8;
#pragma unroll
    for (int ks = 0; ks < 2; ks++) {
        int kb = ks * 16;
        uint32_t ar[4][4], br[4][2];
#pragma unroll
        for (int mi = 0; mi < 4; mi++)
            ldsm_x4(ar[mi], &As[wm + mi * 16 + a_row][kb + a_col]);
#pragma unroll
        for (int ni = 0; ni < 4; ni++)
            ldsm_x2(br[ni], &Bs[wn + ni * 8 + b_row][kb + b_col]);
#pragma unroll
        for (int mi = 0; mi < 4; mi++)
#pragma unroll
            for (int ni = 0; ni < 4; ni++) MMA_BF16(acc[mi][ni], ar[mi], br[ni]);
    }
}

__device__ __forceinline__ bool dless(float a, int ia, float bv, int ib) {
    return (a < bv) || (a == bv && ia < ib);
}

// ---------------- NN: C[M,Nn] = Xa @ Wt^T (+bias)  (round-7 verbatim) ----------------
__global__ __launch_bounds__(256) void mma_nn(const __nv_bfloat16* __restrict__ A,
                                              const __nv_bfloat16* __restrict__ B,
                                              const float* __restrict__ bias,
                                              float* __restrict__ C,
                                              int Kp, int Nn) {
    __shared__ __align__(16) __nv_bfloat16 As[2][128][SMPAD];
    __shared__ __align__(16) __nv_bfloat16 Bs[2][128][SMPAD];
    int tid = threadIdx.x;
    int m0 = blockIdx.y * 128, o0 = blockIdx.x * 128;
    int lane = tid & 31, warp = tid >> 5;
    int wm = (warp & 1) * 64, wn = (warp >> 1) * 32;
    int nk = Kp / 32;

    float acc[4][4][4];
#pragma unroll
    for (int mi = 0; mi < 4; mi++)
#pragma unroll
        for (int ni = 0; ni < 4; ni++)
#pragma unroll
            for (int c = 0; c < 4; c++) acc[mi][ni][c] = 0.f;

    stage_load(As[0], A, m0, Kp, 0, tid);
    stage_load(Bs[0], B, o0, Kp, 0, tid);
    asm volatile("cp.async.commit_group;");

    for (int kt = 0; kt < nk; kt++) {
        if (kt + 1 < nk) {
            stage_load(As[(kt + 1) & 1], A, m0, Kp, (kt + 1) * 32, tid);
            stage_load(Bs[(kt + 1) & 1], B, o0, Kp, (kt + 1) * 32, tid);
            asm volatile("cp.async.commit_group;");
            asm volatile("cp.async.wait_group 1;");
        } else {
            asm volatile("cp.async.wait_group 0;");
        }
        __syncthreads();
        stage_mma(As[kt & 1], Bs[kt & 1], acc, wm, wn, lane);
        __syncthreads();
    }

    int g = lane >> 2, t = lane & 3;
#pragma unroll
    for (int mi = 0; mi < 4; mi++) {
        int row = m0 + wm + mi * 16 + g;
#pragma unroll
        for (int ni = 0; ni < 4; ni++) {
            int col = o0 + wn + ni * 8 + 2 * t;
            if (col < Nn) {
                float b0 = bias ? bias[col] : 0.f;
                float b1 = bias ? bias[col + 1] : 0.f;
                *(float2*)(C + (size_t)row * Nn + col) =
                    make_float2(acc[mi][ni][0] + b0, acc[mi][ni][1] + b1);
                *(float2*)(C + (size_t)(row + 8) * Nn + col) =
                    make_float2(acc[mi][ni][2] + b0, acc[mi][ni][3] + b1);
            }
        }
    }
}

// ---------------- symmetric NT per batch: dot = Xa_b @ Xb_b^T, upper pairs only ----
__global__ __launch_bounds__(256) void mma_nt_sym(const __nv_bfloat16* __restrict__ Xa,
                                                  const __nv_bfloat16* __restrict__ Xb,
                                                  float* __restrict__ Call, int Kp) {
    __shared__ __align__(16) __nv_bfloat16 As[2][128][SMPAD];
    __shared__ __align__(16) __nv_bfloat16 Bs[2][128][SMPAD];
    int b = blockIdx.z;
    // decode upper-triangle pair (ti <= tj)
    int p = blockIdx.x;
    int ti = 0;
    while (p >= NTILES - ti) { p -= NTILES - ti; ti++; }
    int tj = ti + p;
    int m0 = ti * 128, n0 = tj * 128;

    const __nv_bfloat16* Ab = Xa + (size_t)b * NPTS * Kp;
    const __nv_bfloat16* Bb = Xb + (size_t)b * NPTS * Kp;
    float* C = Call + (size_t)b * NPTS * NPTS;
    int tid = threadIdx.x;
    int lane = tid & 31, warp = tid >> 5;
    int wm = (warp & 1) * 64, wn = (warp >> 1) * 32;
    int nk = Kp / 32;

    float acc[4][4][4];
#pragma unroll
    for (int mi = 0; mi < 4; mi++)
#pragma unroll
        for (int ni = 0; ni < 4; ni++)
#pragma unroll
            for (int c = 0; c < 4; c++) acc[mi][ni][c] = 0.f;

    stage_load(As[0], Ab, m0, Kp, 0, tid);
    stage_load(Bs[0], Bb, n0, Kp, 0, tid);
    asm volatile("cp.async.commit_group;");

    for (int kt = 0; kt < nk; kt++) {
        if (kt + 1 < nk) {
            stage_load(As[(kt + 1) & 1], Ab, m0, Kp, (kt + 1) * 32, tid);
            stage_load(Bs[(kt + 1) & 1], Bb, n0, Kp, (kt + 1) * 32, tid);
            asm volatile("cp.async.commit_group;");
            asm volatile("cp.async.wait_group 1;");
        } else {
            asm volatile("cp.async.wait_group 0;");
        }
        __syncthreads();
        stage_mma(As[kt & 1], Bs[kt & 1], acc, wm, wn, lane);
        __syncthreads();
    }

    int g = lane >> 2, t = lane & 3;
#pragma unroll
    for (int mi = 0; mi < 4; mi++) {
        int row = m0 + wm + mi * 16 + g;
#pragma unroll
        for (int ni = 0; ni < 4; ni++) {
            int col = n0 + wn + ni * 8 + 2 * t;
            // upper tile (row, col)
            *(float2*)(C + (size_t)row * NPTS + col) =
                make_float2(acc[mi][ni][0], acc[mi][ni][1]);
            *(float2*)(C + (size_t)(row + 8) * NPTS + col) =
                make_float2(acc[mi][ni][2], acc[mi][ni][3]);
            // mirrored lower tile (col, row) — diagonal tiles: equal-value dup
            if (ti != tj) {
                C[(size_t)col * NPTS + row] = acc[mi][ni][0];
                C[(size_t)(col + 1) * NPTS + row] = acc[mi][ni][1];
                C[(size_t)col * NPTS + row + 8] = acc[mi][ni][2];
                C[(size_t)(col + 1) * NPTS + row + 8] = acc[mi][ni][3];
            }
        }
    }
}

// ---------------- squared norms ----------------
__global__ void sq_kernel(const float* __restrict__ X, int Kd) {
    int i = blockIdx.x * blockDim.x + threadIdx.x;
    if (i < BB * NPTS) {
        const float* p = X + (size_t)i * Kd;
        float s = 0.f;
        for (int f = 0; f < Kd; f++) s += p[f] * p[f];
        g_sq[i] = s;
    }
}

// ---------------- top-K smallest d2 per row, warp per row (round-7 verbatim) ----------------
__global__ void topk_kernel(const float* __restrict__ dotm) {
    int gwarp = (blockIdx.x * blockDim.x + threadIdx.x) >> 5;
    int lane = threadIdx.x & 31;
    if (gwarp >= BB * NPTS) return;
    int b = gwarp / NPTS, i = gwarp % NPTS;
    const float* drow = dotm + ((size_t)b * NPTS + i) * NPTS;
    float sqi = g_sq[b * NPTS + i];

    float best[KNN];
    int bidx[KNN];
#pragma unroll
    for (int m = 0; m < KNN; m++) { best[m] = 3.0e38f; bidx[m] = 0x7fffffff; }

    for (int j = lane; j < NPTS; j += 32) {
        float d2 = sqi + g_sq[b * NPTS + j] - 2.0f * drow[j];
        if (dless(d2, j, best[KNN - 1], bidx[KNN - 1])) {
            int m = KNN - 1;
#pragma unroll
            for (int t = KNN - 1; t > 0; t--) {
                if (m == t && dless(d2, j, best[t - 1], bidx[t - 1])) {
                    best[t] = best[t - 1]; bidx[t] = bidx[t - 1]; m = t - 1;
                }
            }
            best[m] = d2; bidx[m] = j;
        }
    }

    int ptr = 0;
    for (int r = 0; r < KNN; r++) {
        float v = (ptr < KNN) ? best[ptr] : 3.0e38f;
        int jj = (ptr < KNN) ? bidx[ptr] : 0x7fffffff;
        float mv = v; int mj = jj;
#pragma unroll
        for (int off = 16; off > 0; off >>= 1) {
            float ov = __shfl_down_sync(0xffffffffu, mv, off);
            int oj = __shfl_down_sync(0xffffffffu, mj, off);
            if (dless(ov, oj, mv, mj)) { mv = ov; mj = oj; }
        }
        mv = __shfl_sync(0xffffffffu, mv, 0);
        mj = __shfl_sync(0xffffffffu, mj, 0);
        if (jj == mj && v == mv) ptr++;
        if (lane == 0) g_idx[((size_t)b * NPTS + i) * KNN + r] = mj;
    }
}

// ---------------- gather-max edge conv epilogue ----------------
__global__ __launch_bounds__(256) void gathermax_kernel(const float* __restrict__ Z,
                                                        const float* __restrict__ Y,
                                                        const int* __restrict__ idx,
                                                        float* __restrict__ Out,
                                                        int fout) {
    int bn = blockIdx.x;
    int b = bn >> 11;
    const int* ip = idx + (size_t)bn * KNN;
    __shared__ int nb[KNN];
    if (threadIdx.x < KNN) nb[threadIdx.x] = ip[threadIdx.x];
    __syncthreads();

    const float* Yb = Y + (size_t)b * NPTS * fout;
    size_t base = (size_t)bn * fout;

    for (int o = threadIdx.x * 4; o < fout; o += blockDim.x * 4) {
        float4 m = make_float4(-3.0e38f, -3.0e38f, -3.0e38f, -3.0e38f);
#pragma unroll
        for (int k = 0; k < KNN; k++) {
            float4 v = *(const float4*)(Yb + (size_t)nb[k] * fout + o);
            m.x = fmaxf(m.x, v.x);
            m.y = fmaxf(m.y, v.y);
            m.z = fmaxf(m.z, v.z);
            m.w = fmaxf(m.w, v.w);
        }
        float4 z = *(const float4*)(Z + base + o);
        float4 y = *(const float4*)(Y + base + o);
        float4 h;
        h.x = z.x - y.x + m.x;
        h.y = z.y - y.y + m.y;
        h.z = z.z - y.z + m.z;
        h.w = z.w - y.w + m.w;
        h.x = (h.x > 0.f) ? h.x : SLOPE * h.x;
        h.y = (h.y > 0.f) ? h.y : SLOPE * h.y;
        h.z = (h.z > 0.f) ? h.z : SLOPE * h.z;
        h.w = (h.w > 0.f) ? h.w : SLOPE * h.w;
        *(float4*)(Out + base + o) = h;
    }
}

// ---------------- global max pool over N ----------------
__global__ void pool_kernel(const float* __restrict__ H, int Fo) {
    int b = blockIdx.y;
    int o = blockIdx.x * blockDim.x + threadIdx.x;
    if (o < Fo) {
        float m = -3.0e38f;
        for (int n = 0; n < NPTS; n++)
            m = fmaxf(m, H[((size_t)b * NPTS + n) * Fo + o]);
        g_pool[b * Fo + o] = m;
    }
}

// ---------------- small MLP layer ----------------
__global__ void mlp_kernel(const float* __restrict__ A, const float* __restrict__ W,
                           const float* __restrict__ bias, float* __restrict__ C,
                           int M, int Kd, int Nn) {
    for (int i = threadIdx.x; i < M * Nn; i += blockDim.x) {
        int m = i / Nn, o = i % Nn;
        float s = bias[o];
        for (int f = 0; f < Kd; f++) s += A[(size_t)m * Kd + f] * W[(size_t)f * Nn + o];
        C[i] = s;
    }
}

// ---------------- launcher ----------------
extern "C" void kernel_launch(void* const* d_in, const int* in_sizes, int n_in,
                              void* d_out, int out_size) {
    const float* x = (const float*)d_in[0];
    const float* w[5];
    const float* bs[5];
    for (int l = 0; l < 5; l++) {
        w[l] = (const float*)d_in[1 + 2 * l];
        bs[l] = (const float*)d_in[2 + 2 * l];
    }
    const float* m0w = (const float*)d_in[11];
    const float* m0b = (const float*)d_in[12];
    const float* m1w = (const float*)d_in[13];
    const float* m1b = (const float*)d_in[14];
    const float* m2w = (const float*)d_in[15];
    const float* m2b = (const float*)d_in[16];
    float* out = (float*)d_out;

    float *feat_a, *feat_b, *centerp, *dotp, *poolp, *m1p, *m2p;
    __nv_bfloat16 *xap, *xbp, *w1tp, *w2tp;
    int* idxp;
    cudaGetSymbolAddress((void**)&feat_a, g_feat_a);
    cudaGetSymbolAddress((void**)&feat_b, g_feat_b);
    cudaGetSymbolAddress((void**)&centerp, g_center);
    cudaGetSymbolAddress((void**)&dotp, g_dot);
    cudaGetSymbolAddress((void**)&poolp, g_pool);
    cudaGetSymbolAddress((void**)&m1p, g_m1);
    cudaGetSymbolAddress((void**)&m2p, g_m2);
    cudaGetSymbolAddress((void**)&xap, g_xa);
    cudaGetSymbolAddress((void**)&xbp, g_xb);
    cudaGetSymbolAddress((void**)&w1tp, g_w1t);
    cudaGetSymbolAddress((void**)&w2tp, g_w2t);
    cudaGetSymbolAddress((void**)&idxp, g_idx);

    const int fins[5] = {3, 64, 128, 256, 512};
    const int fouts[5] = {64, 128, 256, 512, 1024};
    float* bufs[2] = {feat_a, feat_b};
    const int M = BB * NPTS;

    const float* cur = x;
    for (int l = 0; l < 5; l++) {
        int fin = fins[l], fout = fouts[l];
        int Kp = ((3 * fin + 31) / 32) * 32;
        float* yp = dotp;
        int gx = (fout + 127) / 128;

        convert_x<<<(M * Kp + 255) / 256, 256>>>(cur, xap, xbp, fin, Kp, M);
        convert_w<<<(fout * Kp + 255) / 256, 256>>>(w[l], w1tp, fin, fout, Kp);
        convert_w<<<(fout * Kp + 255) / 256, 256>>>(w[l] + (size_t)fin * fout, w2tp,
                                                    fin, fout, Kp);
        sq_kernel<<<(M + 255) / 256, 256>>>(cur, fin);

        mma_nt_sym<<<dim3(NPAIRS, 1, BB), 256>>>(xap, xbp, dotp, Kp);
        topk_kernel<<<M / 8, 256>>>(dotp);

        mma_nn<<<dim3(gx, M / 128), 256>>>(xap, w1tp, bs[l], centerp, Kp, fout);
        mma_nn<<<dim3(gx, M / 128), 256>>>(xap, w2tp, nullptr, yp, Kp, fout);

        gathermax_kernel<<<M, 256>>>(centerp, yp, idxp, bufs[l & 1], fout);
        cur = bufs[l & 1];
    }

    pool_kernel<<<dim3(MAXF / 256, BB), 256>>>(cur, MAXF);
    mlp_kernel<<<1, 1024>>>(poolp, m0w, m0b, m1p, BB, 1024, 128);
    mlp_kernel<<<1, 512>>>(m1p, m1w, m1b, m2p, BB, 128, 64);
    mlp_kernel<<<1, 256>>>(m2p, m2w, m2b, out, BB, 64, 1);
}

// round 11
// speedup vs baseline: 2.4891x; 1.0301x over previous
#include <cuda_runtime.h>
#include <cuda_bf16.h>
#include <cstdint>

#define BB   8
#define NPTS 2048
#define KNN  10
#define MAXF 1024
#define SLOPE 0.2f
#define KPMAX 1536
#define SMPAD 40
#define NTILES 16
#define NPAIRS 136   // NTILES*(NTILES+1)/2

// ---------------- static scratch ----------------
__device__ float g_feat_a[BB * NPTS * MAXF];
__device__ float g_feat_b[BB * NPTS * MAXF];
__device__ float g_center[BB * NPTS * MAXF];
__device__ float g_dot[(size_t)BB * NPTS * NPTS];   // reused as Y after topk
__device__ __align__(16) __nv_bfloat16 g_xa[(size_t)BB * NPTS * KPMAX];  // (h,l,h)
__device__ __align__(16) __nv_bfloat16 g_xb[(size_t)BB * NPTS * KPMAX];  // (h,h,l)
__device__ __align__(16) __nv_bfloat16 g_w1t[1024 * KPMAX];
__device__ __align__(16) __nv_bfloat16 g_w2t[1024 * KPMAX];
__device__ float g_sq[BB * NPTS];
__device__ int   g_idx[BB * NPTS * KNN];
__device__ float g_pool[BB * MAXF];
__device__ float g_m1[BB * 128];
__device__ float g_m2[BB * 64];

// ---------------- conversions: fp32 -> 3-slot bf16 split ----------------
__global__ void convert_x(const float* __restrict__ X, __nv_bfloat16* __restrict__ Xa,
                          __nv_bfloat16* __restrict__ Xb, int fin, int Kp, int M) {
    int idx = blockIdx.x * blockDim.x + threadIdx.x;
    if (idx >= M * Kp) return;
    int r = idx / Kp, c = idx % Kp;
    __nv_bfloat16 va = __float2bfloat16(0.f), vb = va;
    if (c < 3 * fin) {
        int s = c / fin, cc = c - s * fin;
        float v = X[(size_t)r * fin + cc];
        __nv_bfloat16 h = __float2bfloat16(v);
        __nv_bfloat16 l = __float2bfloat16(v - __bfloat162float(h));
        va = (s == 1) ? l : h;
        vb = (s == 2) ? l : h;
    }
    Xa[(size_t)r * Kp + c] = va;
    Xb[(size_t)r * Kp + c] = vb;
}

__global__ void convert_w(const float* __restrict__ W, __nv_bfloat16* __restrict__ Wt,
                          int fin, int fout, int Kp) {
    int idx = blockIdx.x * blockDim.x + threadIdx.x;
    if (idx >= fout * Kp) return;
    int n = idx / Kp, c = idx % Kp;
    __nv_bfloat16 o = __float2bfloat16(0.f);
    if (c < 3 * fin) {
        int s = c / fin, cc = c - s * fin;
        float v = W[(size_t)cc * fout + n];
        __nv_bfloat16 h = __float2bfloat16(v);
        o = (s == 2) ? __float2bfloat16(v - __bfloat162float(h)) : h;
    }
    Wt[(size_t)n * Kp + c] = o;
}

// ---------------- MMA primitives ----------------
#define MMA_BF16(c, a, b)                                                          \
    asm volatile("mma.sync.aligned.m16n8k16.row.col.f32.bf16.bf16.f32 "            \
                 "{%0,%1,%2,%3}, {%4,%5,%6,%7}, {%8,%9}, {%0,%1,%2,%3};"           \
                 : "+f"(c[0]), "+f"(c[1]), "+f"(c[2]), "+f"(c[3])                  \
                 : "r"(a[0]), "r"(a[1]), "r"(a[2]), "r"(a[3]), "r"(b[0]), "r"(b[1]))

__device__ __forceinline__ void cpa16(void* smem, const void* gmem) {
    uint32_t s = (uint32_t)__cvta_generic_to_shared(smem);
    asm volatile("cp.async.ca.shared.global [%0], [%1], 16;" :: "r"(s), "l"(gmem));
}
__device__ __forceinline__ void ldsm_x4(uint32_t* r, const void* p) {
    uint32_t a = (uint32_t)__cvta_generic_to_shared(p);
    asm volatile("ldmatrix.sync.aligned.m8n8.x4.shared.b16 {%0,%1,%2,%3}, [%4];"
                 : "=r"(r[0]), "=r"(r[1]), "=r"(r[2]), "=r"(r[3]) : "r"(a));
}
__device__ __forceinline__ void ldsm_x2(uint32_t* r, const void* p) {
    uint32_t a = (uint32_t)__cvta_generic_to_shared(p);
    asm volatile("ldmatrix.sync.aligned.m8n8.x2.shared.b16 {%0,%1}, [%2];"
                 : "=r"(r[0]), "=r"(r[1]) : "r"(a));
}

__device__ __forceinline__ void stage_load(__nv_bfloat16 (*S)[SMPAD],
                                           const __nv_bfloat16* __restrict__ src,
                                           int row0, int Kp, int k0, int tid) {
#pragma unroll
    for (int it = 0; it < 2; it++) {
        int e = tid + it * 256;
        int r = e >> 2;
        int cb = (e & 3) * 8;
        cpa16(&S[r][cb], src + (size_t)(row0 + r) * Kp + k0 + cb);
    }
}

__device__ __forceinline__ void stage_mma(const __nv_bfloat16 (*As)[SMPAD],
                                          const __nv_bfloat16 (*Bs)[SMPAD],
                                          float acc[4][4][4], int wm, int wn, int lane) {
    int a_row = (lane & 15);
    int a_col = (lane >> 4) * 8;
    int b_row = (lane & 7);
    int b_col = ((lane >> 3) & 1) * 8;
#pragma unroll
    for (int ks = 0; ks < 2; ks++) {
        int kb = ks * 16;
        uint32_t ar[4][4], br[4][2];
#pragma unroll
        for (int mi = 0; mi < 4; mi++)
            ldsm_x4(ar[mi], &As[wm + mi * 16 + a_row][kb + a_col]);
#pragma unroll
        for (int ni = 0; ni < 4; ni++)
            ldsm_x2(br[ni], &Bs[wn + ni * 8 + b_row][kb + b_col]);
#pragma unroll
        for (int mi = 0; mi < 4; mi++)
#pragma unroll
            for (int ni = 0; ni < 4; ni++) MMA_BF16(acc[mi][ni], ar[mi], br[ni]);
    }
}

// 3-stage pipeline, single __syncthreads per k-iteration.
// Safety: prefetch for stage kt+2 (buffer (kt+2)%3 == (kt-1)%3) is issued
// AFTER the sync, and all readers of that buffer (iteration kt-1) completed
// before that same sync.
#define KLOOP3(Aptr, Bptr, m0_, n0_)                                               \
    stage_load(As[0], Aptr, m0_, Kp, 0, tid);                                      \
    stage_load(Bs[0], Bptr, n0_, Kp, 0, tid);                                      \
    asm volatile("cp.async.commit_group;");                                        \
    if (nk > 1) {                                                                  \
        stage_load(As[1], Aptr, m0_, Kp, 32, tid);                                 \
        stage_load(Bs[1], Bptr, n0_, Kp, 32, tid);                                 \
        asm volatile("cp.async.commit_group;");                                    \
    }                                                                              \
    for (int kt = 0; kt < nk; kt++) {                                              \
        if (kt + 1 < nk) asm volatile("cp.async.wait_group 1;");                   \
        else             asm volatile("cp.async.wait_group 0;");                   \
        __syncthreads();                                                           \
        if (kt + 2 < nk) {                                                         \
            int sprev = (kt + 2) % 3;                                              \
            stage_load(As[sprev], Aptr, m0_, Kp, (kt + 2) * 32, tid);              \
            stage_load(Bs[sprev], Bptr, n0_, Kp, (kt + 2) * 32, tid);              \
            asm volatile("cp.async.commit_group;");                                \
        }                                                                          \
        stage_mma(As[kt % 3], Bs[kt % 3], acc, wm, wn, lane);                      \
    }

__device__ __forceinline__ bool dless(float a, int ia, float bv, int ib) {
    return (a < bv) || (a == bv && ia < ib);
}

// ---------------- NN: C[M,Nn] = Xa @ Wt^T (+bias) ----------------
__global__ __launch_bounds__(256) void mma_nn(const __nv_bfloat16* __restrict__ A,
                                              const __nv_bfloat16* __restrict__ B,
                                              const float* __restrict__ bias,
                                              float* __restrict__ C,
                                              int Kp, int Nn) {
    __shared__ __align__(16) __nv_bfloat16 As[3][128][SMPAD];
    __shared__ __align__(16) __nv_bfloat16 Bs[3][128][SMPAD];
    int tid = threadIdx.x;
    int m0 = blockIdx.y * 128, o0 = blockIdx.x * 128;
    int lane = tid & 31, warp = tid >> 5;
    int wm = (warp & 1) * 64, wn = (warp >> 1) * 32;
    int nk = Kp / 32;

    float acc[4][4][4];
#pragma unroll
    for (int mi = 0; mi < 4; mi++)
#pragma unroll
        for (int ni = 0; ni < 4; ni++)
#pragma unroll
            for (int c = 0; c < 4; c++) acc[mi][ni][c] = 0.f;

    KLOOP3(A, B, m0, o0)

    int g = lane >> 2, t = lane & 3;
#pragma unroll
    for (int mi = 0; mi < 4; mi++) {
        int row = m0 + wm + mi * 16 + g;
#pragma unroll
        for (int ni = 0; ni < 4; ni++) {
            int col = o0 + wn + ni * 8 + 2 * t;
            if (col < Nn) {
                float b0 = bias ? bias[col] : 0.f;
                float b1 = bias ? bias[col + 1] : 0.f;
                *(float2*)(C + (size_t)row * Nn + col) =
                    make_float2(acc[mi][ni][0] + b0, acc[mi][ni][1] + b1);
                *(float2*)(C + (size_t)(row + 8) * Nn + col) =
                    make_float2(acc[mi][ni][2] + b0, acc[mi][ni][3] + b1);
            }
        }
    }
}

// ---------------- symmetric NT per batch: dot = Xa_b @ Xb_b^T, upper pairs only ----
__global__ __launch_bounds__(256) void mma_nt_sym(const __nv_bfloat16* __restrict__ Xa,
                                                  const __nv_bfloat16* __restrict__ Xb,
                                                  float* __restrict__ Call, int Kp) {
    __shared__ __align__(16) __nv_bfloat16 As[3][128][SMPAD];
    __shared__ __align__(16) __nv_bfloat16 Bs[3][128][SMPAD];
    int b = blockIdx.z;
    int p = blockIdx.x;
    int ti = 0;
    while (p >= NTILES - ti) { p -= NTILES - ti; ti++; }
    int tj = ti + p;
    int m0 = ti * 128, n0 = tj * 128;

    const __nv_bfloat16* Ab = Xa + (size_t)b * NPTS * Kp;
    const __nv_bfloat16* Bb = Xb + (size_t)b * NPTS * Kp;
    float* C = Call + (size_t)b * NPTS * NPTS;
    int tid = threadIdx.x;
    int lane = tid & 31, warp = tid >> 5;
    int wm = (warp & 1) * 64, wn = (warp >> 1) * 32;
    int nk = Kp / 32;

    float acc[4][4][4];
#pragma unroll
    for (int mi = 0; mi < 4; mi++)
#pragma unroll
        for (int ni = 0; ni < 4; ni++)
#pragma unroll
            for (int c = 0; c < 4; c++) acc[mi][ni][c] = 0.f;

    KLOOP3(Ab, Bb, m0, n0)

    int g = lane >> 2, t = lane & 3;
#pragma unroll
    for (int mi = 0; mi < 4; mi++) {
        int row = m0 + wm + mi * 16 + g;
#pragma unroll
        for (int ni = 0; ni < 4; ni++) {
            int col = n0 + wn + ni * 8 + 2 * t;
            *(float2*)(C + (size_t)row * NPTS + col) =
                make_float2(acc[mi][ni][0], acc[mi][ni][1]);
            *(float2*)(C + (size_t)(row + 8) * NPTS + col) =
                make_float2(acc[mi][ni][2], acc[mi][ni][3]);
            if (ti != tj) {
                C[(size_t)col * NPTS + row] = acc[mi][ni][0];
                C[(size_t)(col + 1) * NPTS + row] = acc[mi][ni][1];
                C[(size_t)col * NPTS + row + 8] = acc[mi][ni][2];
                C[(size_t)(col + 1) * NPTS + row + 8] = acc[mi][ni][3];
            }
        }
    }
}

// ---------------- squared norms ----------------
__global__ void sq_kernel(const float* __restrict__ X, int Kd) {
    int i = blockIdx.x * blockDim.x + threadIdx.x;
    if (i < BB * NPTS) {
        const float* p = X + (size_t)i * Kd;
        float s = 0.f;
        for (int f = 0; f < Kd; f++) s += p[f] * p[f];
        g_sq[i] = s;
    }
}

// ---------------- top-K smallest d2 per row, warp per row ----------------
__global__ void topk_kernel(const float* __restrict__ dotm) {
    int gwarp = (blockIdx.x * blockDim.x + threadIdx.x) >> 5;
    int lane = threadIdx.x & 31;
    if (gwarp >= BB * NPTS) return;
    int b = gwarp / NPTS, i = gwarp % NPTS;
    const float* drow = dotm + ((size_t)b * NPTS + i) * NPTS;
    float sqi = g_sq[b * NPTS + i];

    float best[KNN];
    int bidx[KNN];
#pragma unroll
    for (int m = 0; m < KNN; m++) { best[m] = 3.0e38f; bidx[m] = 0x7fffffff; }

    for (int j = lane; j < NPTS; j += 32) {
        float d2 = sqi + g_sq[b * NPTS + j] - 2.0f * drow[j];
        if (dless(d2, j, best[KNN - 1], bidx[KNN - 1])) {
            int m = KNN - 1;
#pragma unroll
            for (int t = KNN - 1; t > 0; t--) {
                if (m == t && dless(d2, j, best[t - 1], bidx[t - 1])) {
                    best[t] = best[t - 1]; bidx[t] = bidx[t - 1]; m = t - 1;
                }
            }
            best[m] = d2; bidx[m] = j;
        }
    }

    int ptr = 0;
    for (int r = 0; r < KNN; r++) {
        float v = (ptr < KNN) ? best[ptr] : 3.0e38f;
        int jj = (ptr < KNN) ? bidx[ptr] : 0x7fffffff;
        float mv = v; int mj = jj;
#pragma unroll
        for (int off = 16; off > 0; off >>= 1) {
            float ov = __shfl_down_sync(0xffffffffu, mv, off);
            int oj = __shfl_down_sync(0xffffffffu, mj, off);
            if (dless(ov, oj, mv, mj)) { mv = ov; mj = oj; }
        }
        mv = __shfl_sync(0xffffffffu, mv, 0);
        mj = __shfl_sync(0xffffffffu, mj, 0);
        if (jj == mj && v == mv) ptr++;
        if (lane == 0) g_idx[((size_t)b * NPTS + i) * KNN + r] = mj;
    }
}

// ---------------- gather-max edge conv epilogue (packed blocks) ----------------
// block handles ppb points; ppb * (fout/4) == 256.
__global__ __launch_bounds__(256) void gathermax_kernel(const float* __restrict__ Z,
                                                        const float* __restrict__ Y,
                                                        const int* __restrict__ idx,
                                                        float* __restrict__ Out,
                                                        int fout, int ppb) {
    __shared__ int nb[16 * KNN];
    int p0 = blockIdx.x * ppb;
    for (int e = threadIdx.x; e < ppb * KNN; e += blockDim.x)
        nb[e] = idx[(size_t)(p0 + e / KNN) * KNN + e % KNN];
    __syncthreads();

    int tpp = fout >> 2;                 // threads per point
    int lp = threadIdx.x / tpp;          // local point (0..ppb-1)
    int o = (threadIdx.x - lp * tpp) * 4;

    int bn = p0 + lp;
    int b = bn >> 11;
    const float* Yb = Y + (size_t)b * NPTS * fout;
    size_t base = (size_t)bn * fout;
    const int* nbp = nb + lp * KNN;

    float4 m = make_float4(-3.0e38f, -3.0e38f, -3.0e38f, -3.0e38f);
#pragma unroll
    for (int k = 0; k < KNN; k++) {
        float4 v = *(const float4*)(Yb + (size_t)nbp[k] * fout + o);
        m.x = fmaxf(m.x, v.x);
        m.y = fmaxf(m.y, v.y);
        m.z = fmaxf(m.z, v.z);
        m.w = fmaxf(m.w, v.w);
    }
    float4 z = *(const float4*)(Z + base + o);
    float4 y = *(const float4*)(Y + base + o);
    float4 h;
    h.x = z.x - y.x + m.x;
    h.y = z.y - y.y + m.y;
    h.z = z.z - y.z + m.z;
    h.w = z.w - y.w + m.w;
    h.x = (h.x > 0.f) ? h.x : SLOPE * h.x;
    h.y = (h.y > 0.f) ? h.y : SLOPE * h.y;
    h.z = (h.z > 0.f) ? h.z : SLOPE * h.z;
    h.w = (h.w > 0.f) ? h.w : SLOPE * h.w;
    *(float4*)(Out + base + o) = h;
}

// ---------------- global max pool over N ----------------
__global__ void pool_kernel(const float* __restrict__ H, int Fo) {
    int b = blockIdx.y;
    int o = blockIdx.x * blockDim.x + threadIdx.x;
    if (o < Fo) {
        float m = -3.0e38f;
        for (int n = 0; n < NPTS; n++)
            m = fmaxf(m, H[((size_t)b * NPTS + n) * Fo + o]);
        g_pool[b * Fo + o] = m;
    }
}

// ---------------- small MLP layer ----------------
__global__ void mlp_kernel(const float* __restrict__ A, const float* __restrict__ W,
                           const float* __restrict__ bias, float* __restrict__ C,
                           int M, int Kd, int Nn) {
    for (int i = threadIdx.x; i < M * Nn; i += blockDim.x) {
        int m = i / Nn, o = i % Nn;
        float s = bias[o];
        for (int f = 0; f < Kd; f++) s += A[(size_t)m * Kd + f] * W[(size_t)f * Nn + o];
        C[i] = s;
    }
}

// ---------------- launcher ----------------
extern "C" void kernel_launch(void* const* d_in, const int* in_sizes, int n_in,
                              void* d_out, int out_size) {
    const float* x = (const float*)d_in[0];
    const float* w[5];
    const float* bs[5];
    for (int l = 0; l < 5; l++) {
        w[l] = (const float*)d_in[1 + 2 * l];
        bs[l] = (const float*)d_in[2 + 2 * l];
    }
    const float* m0w = (const float*)d_in[11];
    const float* m0b = (const float*)d_in[12];
    const float* m1w = (const float*)d_in[13];
    const float* m1b = (const float*)d_in[14];
    const float* m2w = (const float*)d_in[15];
    const float* m2b = (const float*)d_in[16];
    float* out = (float*)d_out;

    float *feat_a, *feat_b, *centerp, *dotp, *poolp, *m1p, *m2p;
    __nv_bfloat16 *xap, *xbp, *w1tp, *w2tp;
    int* idxp;
    cudaGetSymbolAddress((void**)&feat_a, g_feat_a);
    cudaGetSymbolAddress((void**)&feat_b, g_feat_b);
    cudaGetSymbolAddress((void**)&centerp, g_center);
    cudaGetSymbolAddress((void**)&dotp, g_dot);
    cudaGetSymbolAddress((void**)&poolp, g_pool);
    cudaGetSymbolAddress((void**)&m1p, g_m1);
    cudaGetSymbolAddress((void**)&m2p, g_m2);
    cudaGetSymbolAddress((void**)&xap, g_xa);
    cudaGetSymbolAddress((void**)&xbp, g_xb);
    cudaGetSymbolAddress((void**)&w1tp, g_w1t);
    cudaGetSymbolAddress((void**)&w2tp, g_w2t);
    cudaGetSymbolAddress((void**)&idxp, g_idx);

    const int fins[5] = {3, 64, 128, 256, 512};
    const int fouts[5] = {64, 128, 256, 512, 1024};
    float* bufs[2] = {feat_a, feat_b};
    const int M = BB * NPTS;

    const float* cur = x;
    for (int l = 0; l < 5; l++) {
        int fin = fins[l], fout = fouts[l];
        int Kp = ((3 * fin + 31) / 32) * 32;
        float* yp = dotp;
        int gx = (fout + 127) / 128;
        int ppb = 1024 / fout;     // 16,8,4,2,1

        convert_x<<<(M * Kp + 255) / 256, 256>>>(cur, xap, xbp, fin, Kp, M);
        convert_w<<<(fout * Kp + 255) / 256, 256>>>(w[l], w1tp, fin, fout, Kp);
        convert_w<<<(fout * Kp + 255) / 256, 256>>>(w[l] + (size_t)fin * fout, w2tp,
                                                    fin, fout, Kp);
        sq_kernel<<<(M + 255) / 256, 256>>>(cur, fin);

        mma_nt_sym<<<dim3(NPAIRS, 1, BB), 256>>>(xap, xbp, dotp, Kp);
        topk_kernel<<<M / 8, 256>>>(dotp);

        mma_nn<<<dim3(gx, M / 128), 256>>>(xap, w1tp, bs[l], centerp, Kp, fout);
        mma_nn<<<dim3(gx, M / 128), 256>>>(xap, w2tp, nullptr, yp, Kp, fout);

        gathermax_kernel<<<M / ppb, 256>>>(centerp, yp, idxp, bufs[l & 1], fout, ppb);
        cur = bufs[l & 1];
    }

    pool_kernel<<<dim3(MAXF / 256, BB), 256>>>(cur, MAXF);
    mlp_kernel<<<1, 1024>>>(poolp, m0w, m0b, m1p, BB, 1024, 128);
    mlp_kernel<<<1, 512>>>(m1p, m1w, m1b, m2p, BB, 128, 64);
    mlp_kernel<<<1, 256>>>(m2p, m2w, m2b, out, BB, 64, 1);
}

// round 14
// speedup vs baseline: 2.6229x; 1.0538x over previous
#include <cuda_runtime.h>
#include <cuda_bf16.h>
#include <cstdint>

#define BB   8
#define NPTS 2048
#define KNN  10
#define MAXF 1024
#define SLOPE 0.2f
#define KPMAX 1536
#define SMPAD 40
#define NTILES 16
#define NPAIRS 136

// ---------------- static scratch ----------------
__device__ float g_feat_a[BB * NPTS * MAXF];
__device__ float g_feat_b[BB * NPTS * MAXF];
__device__ float g_center[BB * NPTS * MAXF];
__device__ float g_dot[(size_t)BB * NPTS * NPTS];   // reused as Y after topk
__device__ __align__(16) __nv_bfloat16 g_xa[(size_t)BB * NPTS * KPMAX];  // (h,l,h)
__device__ __align__(16) __nv_bfloat16 g_xb[(size_t)BB * NPTS * KPMAX];  // (h,h,l)
__device__ __align__(16) __nv_bfloat16 g_w12t[2048 * KPMAX];             // W1^T ‖ W2^T
__device__ float g_sq[BB * NPTS];
__device__ int   g_idx[BB * NPTS * KNN];
__device__ float g_pool[BB * MAXF];

// ---------------- conversions: fp32 -> 3-slot bf16 split ----------------
__global__ void convert_x(const float* __restrict__ X, __nv_bfloat16* __restrict__ Xa,
                          __nv_bfloat16* __restrict__ Xb, int fin, int Kp, int M) {
    int idx = blockIdx.x * blockDim.x + threadIdx.x;
    if (idx >= M * Kp) return;
    int r = idx / Kp, c = idx % Kp;
    __nv_bfloat16 va = __float2bfloat16(0.f), vb = va;
    if (c < 3 * fin) {
        int s = c / fin, cc = c - s * fin;
        float v = X[(size_t)r * fin + cc];
        __nv_bfloat16 h = __float2bfloat16(v);
        __nv_bfloat16 l = __float2bfloat16(v - __bfloat162float(h));
        va = (s == 1) ? l : h;
        vb = (s == 2) ? l : h;
    }
    Xa[(size_t)r * Kp + c] = va;
    Xb[(size_t)r * Kp + c] = vb;
}

// combined W1^T (rows [0,fout)) and W2^T (rows [fout,2fout)), 3-slot (h,h,l)
__global__ void convert_w12(const float* __restrict__ W, __nv_bfloat16* __restrict__ Wt,
                            int fin, int fout, int Kp) {
    int idx = blockIdx.x * blockDim.x + threadIdx.x;
    if (idx >= 2 * fout * Kp) return;
    int n = idx / Kp, c = idx % Kp;
    const float* src = (n < fout) ? W : W + (size_t)fin * fout;
    int nn = (n < fout) ? n : n - fout;
    __nv_bfloat16 o = __float2bfloat16(0.f);
    if (c < 3 * fin) {
        int s = c / fin, cc = c - s * fin;
        float v = src[(size_t)cc * fout + nn];
        __nv_bfloat16 h = __float2bfloat16(v);
        o = (s == 2) ? __float2bfloat16(v - __bfloat162float(h)) : h;
    }
    Wt[(size_t)n * Kp + c] = o;
}

// ---------------- MMA primitives ----------------
#define MMA_BF16(c, a, b)                                                          \
    asm volatile("mma.sync.aligned.m16n8k16.row.col.f32.bf16.bf16.f32 "            \
                 "{%0,%1,%2,%3}, {%4,%5,%6,%7}, {%8,%9}, {%0,%1,%2,%3};"           \
                 : "+f"(c[0]), "+f"(c[1]), "+f"(c[2]), "+f"(c[3])                  \
                 : "r"(a[0]), "r"(a[1]), "r"(a[2]), "r"(a[3]), "r"(b[0]), "r"(b[1]))

__device__ __forceinline__ void cpa16(void* smem, const void* gmem) {
    uint32_t s = (uint32_t)__cvta_generic_to_shared(smem);
    asm volatile("cp.async.cg.shared.global [%0], [%1], 16;" :: "r"(s), "l"(gmem));
}
__device__ __forceinline__ void ldsm_x4(uint32_t* r, const void* p) {
    uint32_t a = (uint32_t)__cvta_generic_to_shared(p);
    asm volatile("ldmatrix.sync.aligned.m8n8.x4.shared.b16 {%0,%1,%2,%3}, [%4];"
                 : "=r"(r[0]), "=r"(r[1]), "=r"(r[2]), "=r"(r[3]) : "r"(a));
}
__device__ __forceinline__ void ldsm_x2(uint32_t* r, const void* p) {
    uint32_t a = (uint32_t)__cvta_generic_to_shared(p);
    asm volatile("ldmatrix.sync.aligned.m8n8.x2.shared.b16 {%0,%1}, [%2];"
                 : "=r"(r[0]), "=r"(r[1]) : "r"(a));
}

__device__ __forceinline__ void stage_load(__nv_bfloat16 (*S)[SMPAD],
                                           const __nv_bfloat16* __restrict__ src,
                                           int row0, int Kp, int k0, int tid) {
#pragma unroll
    for (int it = 0; it < 2; it++) {
        int e = tid + it * 256;
        int r = e >> 2;
        int cb = (e & 3) * 8;
        cpa16(&S[r][cb], src + (size_t)(row0 + r) * Kp + k0 + cb);
    }
}

__device__ __forceinline__ void stage_mma(const __nv_bfloat16 (*As)[SMPAD],
                                          const __nv_bfloat16 (*Bs)[SMPAD],
                                          float acc[4][4][4], int wm, int wn, int lane) {
    int a_row = (lane & 15);
    int a_col = (lane >> 4) * 8;
    int b_row = (lane & 7);
    int b_col = ((lane >> 3) & 1) * 8;
#pragma unroll
    for (int ks = 0; ks < 2; ks++) {
        int kb = ks * 16;
        uint32_t ar[4][4], br[4][2];
#pragma unroll
        for (int mi = 0; mi < 4; mi++)
            ldsm_x4(ar[mi], &As[wm + mi * 16 + a_row][kb + a_col]);
#pragma unroll
        for (int ni = 0; ni < 4; ni++)
            ldsm_x2(br[ni], &Bs[wn + ni * 8 + b_row][kb + b_col]);
#pragma unroll
        for (int mi = 0; mi < 4; mi++)
#pragma unroll
            for (int ni = 0; ni < 4; ni++) MMA_BF16(acc[mi][ni], ar[mi], br[ni]);
    }
}

// 3-stage pipeline, single __syncthreads per k-iteration (validated round 11)
#define KLOOP3(Aptr, Bptr, m0_, n0_)                                               \
    stage_load(As[0], Aptr, m0_, Kp, 0, tid);                                      \
    stage_load(Bs[0], Bptr, n0_, Kp, 0, tid);                                      \
    asm volatile("cp.async.commit_group;");                                        \
    if (nk > 1) {                                                                  \
        stage_load(As[1], Aptr, m0_, Kp, 32, tid);                                 \
        stage_load(Bs[1], Bptr, n0_, Kp, 32, tid);                                 \
        asm volatile("cp.async.commit_group;");                                    \
    }                                                                              \
    for (int kt = 0; kt < nk; kt++) {                                              \
        if (kt + 1 < nk) asm volatile("cp.async.wait_group 1;");                   \
        else             asm volatile("cp.async.wait_group 0;");                   \
        __syncthreads();                                                           \
        if (kt + 2 < nk) {                                                         \
            int sprev = (kt + 2) % 3;                                              \
            stage_load(As[sprev], Aptr, m0_, Kp, (kt + 2) * 32, tid);              \
            stage_load(Bs[sprev], Bptr, n0_, Kp, (kt + 2) * 32, tid);              \
            asm volatile("cp.async.commit_group;");                                \
        }                                                                          \
        stage_mma(As[kt % 3], Bs[kt % 3], acc, wm, wn, lane);                      \
    }

__device__ __forceinline__ bool dless(float a, int ia, float bv, int ib) {
    return (a < bv) || (a == bv && ia < ib);
}

__device__ __forceinline__ void tk_insert(float d2, int j, float* best, int* bidx) {
    if (dless(d2, j, best[KNN - 1], bidx[KNN - 1])) {
        int m = KNN - 1;
#pragma unroll
        for (int tt = KNN - 1; tt > 0; tt--) {
            if (m == tt && dless(d2, j, best[tt - 1], bidx[tt - 1])) {
                best[tt] = best[tt - 1]; bidx[tt] = bidx[tt - 1]; m = tt - 1;
            }
        }
        best[m] = d2; bidx[m] = j;
    }
}

// ---------------- NN fused Z/Y: [Z|Y] = Xa @ [W1t|W2t]^T ----------------
__global__ __launch_bounds__(256) void mma_nn_zy(const __nv_bfloat16* __restrict__ A,
                                                 const __nv_bfloat16* __restrict__ B,
                                                 const float* __restrict__ bias,
                                                 float* __restrict__ Z,
                                                 float* __restrict__ Y,
                                                 int Kp, int fout) {
    __shared__ __align__(16) __nv_bfloat16 As[3][128][SMPAD];
    __shared__ __align__(16) __nv_bfloat16 Bs[3][128][SMPAD];
    int tid = threadIdx.x;
    int m0 = blockIdx.y * 128, o0 = blockIdx.x * 128;
    int lane = tid & 31, warp = tid >> 5;
    int wm = (warp & 1) * 64, wn = (warp >> 1) * 32;
    int nk = Kp / 32;

    float acc[4][4][4];
#pragma unroll
    for (int mi = 0; mi < 4; mi++)
#pragma unroll
        for (int ni = 0; ni < 4; ni++)
#pragma unroll
            for (int c = 0; c < 4; c++) acc[mi][ni][c] = 0.f;

    KLOOP3(A, B, m0, o0)

    int g = lane >> 2, t = lane & 3;
#pragma unroll
    for (int mi = 0; mi < 4; mi++) {
        int row = m0 + wm + mi * 16 + g;
#pragma unroll
        for (int ni = 0; ni < 4; ni++) {
            int col = o0 + wn + ni * 8 + 2 * t;
            if (col < fout) {
                float b0 = bias[col], b1 = bias[col + 1];
                *(float2*)(Z + (size_t)row * fout + col) =
                    make_float2(acc[mi][ni][0] + b0, acc[mi][ni][1] + b1);
                *(float2*)(Z + (size_t)(row + 8) * fout + col) =
                    make_float2(acc[mi][ni][2] + b0, acc[mi][ni][3] + b1);
            } else {
                int yc = col - fout;
                *(float2*)(Y + (size_t)row * fout + yc) =
                    make_float2(acc[mi][ni][0], acc[mi][ni][1]);
                *(float2*)(Y + (size_t)(row + 8) * fout + yc) =
                    make_float2(acc[mi][ni][2], acc[mi][ni][3]);
            }
        }
    }
}

// ---------------- symmetric NT per batch: dot = Xa_b @ Xb_b^T, upper pairs only ----
__global__ __launch_bounds__(256) void mma_nt_sym(const __nv_bfloat16* __restrict__ Xa,
                                                  const __nv_bfloat16* __restrict__ Xb,
                                                  float* __restrict__ Call, int Kp) {
    __shared__ __align__(16) __nv_bfloat16 As[3][128][SMPAD];
    __shared__ __align__(16) __nv_bfloat16 Bs[3][128][SMPAD];
    int b = blockIdx.z;
    int p = blockIdx.x;
    int ti = 0;
    while (p >= NTILES - ti) { p -= NTILES - ti; ti++; }
    int tj = ti + p;
    int m0 = ti * 128, n0 = tj * 128;

    const __nv_bfloat16* Ab = Xa + (size_t)b * NPTS * Kp;
    const __nv_bfloat16* Bb = Xb + (size_t)b * NPTS * Kp;
    float* C = Call + (size_t)b * NPTS * NPTS;
    int tid = threadIdx.x;
    int lane = tid & 31, warp = tid >> 5;
    int wm = (warp & 1) * 64, wn = (warp >> 1) * 32;
    int nk = Kp / 32;

    float acc[4][4][4];
#pragma unroll
    for (int mi = 0; mi < 4; mi++)
#pragma unroll
        for (int ni = 0; ni < 4; ni++)
#pragma unroll
            for (int c = 0; c < 4; c++) acc[mi][ni][c] = 0.f;

    KLOOP3(Ab, Bb, m0, n0)

    int g = lane >> 2, t = lane & 3;
#pragma unroll
    for (int mi = 0; mi < 4; mi++) {
        int row = m0 + wm + mi * 16 + g;
#pragma unroll
        for (int ni = 0; ni < 4; ni++) {
            int col = n0 + wn + ni * 8 + 2 * t;
            *(float2*)(C + (size_t)row * NPTS + col) =
                make_float2(acc[mi][ni][0], acc[mi][ni][1]);
            *(float2*)(C + (size_t)(row + 8) * NPTS + col) =
                make_float2(acc[mi][ni][2], acc[mi][ni][3]);
            if (ti != tj) {
                C[(size_t)col * NPTS + row] = acc[mi][ni][0];
                C[(size_t)(col + 1) * NPTS + row] = acc[mi][ni][1];
                C[(size_t)col * NPTS + row + 8] = acc[mi][ni][2];
                C[(size_t)(col + 1) * NPTS + row + 8] = acc[mi][ni][3];
            }
        }
    }
}

// ---------------- squared norms ----------------
__global__ void sq_kernel(const float* __restrict__ X, int Kd) {
    int i = blockIdx.x * blockDim.x + threadIdx.x;
    if (i < BB * NPTS) {
        const float* p = X + (size_t)i * Kd;
        float s = 0.f;
        for (int f = 0; f < Kd; f++) s += p[f] * p[f];
        g_sq[i] = s;
    }
}

// ---------------- top-K smallest d2 per row, warp per row, float4 reads ----------------
__global__ void topk_kernel(const float* __restrict__ dotm) {
    int gwarp = (blockIdx.x * blockDim.x + threadIdx.x) >> 5;
    int lane = threadIdx.x & 31;
    if (gwarp >= BB * NPTS) return;
    int b = gwarp / NPTS, i = gwarp % NPTS;
    const float* drow = dotm + ((size_t)b * NPTS + i) * NPTS;
    const float* sqb = g_sq + b * NPTS;
    float sqi = sqb[i];

    float best[KNN];
    int bidx[KNN];
#pragma unroll
    for (int m = 0; m < KNN; m++) { best[m] = 3.0e38f; bidx[m] = 0x7fffffff; }

    for (int j0 = lane * 4; j0 < NPTS; j0 += 128) {
        float4 d = *(const float4*)(drow + j0);
        float4 s = *(const float4*)(sqb + j0);
        tk_insert(sqi + s.x - 2.0f * d.x, j0 + 0, best, bidx);
        tk_insert(sqi + s.y - 2.0f * d.y, j0 + 1, best, bidx);
        tk_insert(sqi + s.z - 2.0f * d.z, j0 + 2, best, bidx);
        tk_insert(sqi + s.w - 2.0f * d.w, j0 + 3, best, bidx);
    }

    int ptr = 0;
    for (int r = 0; r < KNN; r++) {
        float v = (ptr < KNN) ? best[ptr] : 3.0e38f;
        int jj = (ptr < KNN) ? bidx[ptr] : 0x7fffffff;
        float mv = v; int mj = jj;
#pragma unroll
        for (int off = 16; off > 0; off >>= 1) {
            float ov = __shfl_down_sync(0xffffffffu, mv, off);
            int oj = __shfl_down_sync(0xffffffffu, mj, off);
            if (dless(ov, oj, mv, mj)) { mv = ov; mj = oj; }
        }
        mv = __shfl_sync(0xffffffffu, mv, 0);
        mj = __shfl_sync(0xffffffffu, mj, 0);
        if (jj == mj && v == mv) ptr++;
        if (lane == 0) g_idx[(size_t)gwarp * KNN + r] = mj;
    }
}

// ---------------- gather-max edge conv epilogue (packed blocks) ----------------
__global__ __launch_bounds__(256) void gathermax_kernel(const float* __restrict__ Z,
                                                        const float* __restrict__ Y,
                                                        const int* __restrict__ idx,
                                                        float* __restrict__ Out,
                                                        int fout, int ppb) {
    __shared__ int nb[16 * KNN];
    int p0 = blockIdx.x * ppb;
    for (int e = threadIdx.x; e < ppb * KNN; e += blockDim.x)
        nb[e] = idx[(size_t)(p0 + e / KNN) * KNN + e % KNN];
    __syncthreads();

    int tpp = fout >> 2;
    int lp = threadIdx.x / tpp;
    int o = (threadIdx.x - lp * tpp) * 4;

    int bn = p0 + lp;
    int b = bn >> 11;
    const float* Yb = Y + (size_t)b * NPTS * fout;
    size_t base = (size_t)bn * fout;
    const int* nbp = nb + lp * KNN;

    float4 m = make_float4(-3.0e38f, -3.0e38f, -3.0e38f, -3.0e38f);
#pragma unroll
    for (int k = 0; k < KNN; k++) {
        float4 v = *(const float4*)(Yb + (size_t)nbp[k] * fout + o);
        m.x = fmaxf(m.x, v.x);
        m.y = fmaxf(m.y, v.y);
        m.z = fmaxf(m.z, v.z);
        m.w = fmaxf(m.w, v.w);
    }
    float4 z = *(const float4*)(Z + base + o);
    float4 y = *(const float4*)(Y + base + o);
    float4 h;
    h.x = z.x - y.x + m.x;
    h.y = z.y - y.y + m.y;
    h.z = z.z - y.z + m.z;
    h.w = z.w - y.w + m.w;
    h.x = (h.x > 0.f) ? h.x : SLOPE * h.x;
    h.y = (h.y > 0.f) ? h.y : SLOPE * h.y;
    h.z = (h.z > 0.f) ? h.z : SLOPE * h.z;
    h.w = (h.w > 0.f) ? h.w : SLOPE * h.w;
    *(float4*)(Out + base + o) = h;
}

// ---------------- global max pool over N ----------------
__global__ void pool_kernel(const float* __restrict__ H, int Fo) {
    int b = blockIdx.y;
    int o = blockIdx.x * blockDim.x + threadIdx.x;
    if (o < Fo) {
        float m = -3.0e38f;
        for (int n = 0; n < NPTS; n++)
            m = fmaxf(m, H[((size_t)b * NPTS + n) * Fo + o]);
        g_pool[b * Fo + o] = m;
    }
}

// ---------------- fused 3-layer MLP head (one block, 1024 threads) ----------------
__global__ __launch_bounds__(1024) void mlp3_kernel(const float* __restrict__ A,
                                                    const float* __restrict__ w0,
                                                    const float* __restrict__ b0,
                                                    const float* __restrict__ w1,
                                                    const float* __restrict__ b1,
                                                    const float* __restrict__ w2,
                                                    const float* __restrict__ b2,
                                                    float* __restrict__ out) {
    __shared__ float s1[BB * 128];
    __shared__ float s2[BB * 64];
    int tid = threadIdx.x;

    // stage 1: (8,1024) @ (1024,128)
    {
        int m = tid >> 7, o = tid & 127;
        const float* a = A + m * 1024;
        float s = b0[o];
        for (int f = 0; f < 1024; f++) s += a[f] * w0[f * 128 + o];
        s1[m * 128 + o] = s;
    }
    __syncthreads();
    // stage 2: (8,128) @ (128,64)
    if (tid < BB * 64) {
        int m = tid >> 6, o = tid & 63;
        const float* a = s1 + m * 128;
        float s = b1[o];
        for (int f = 0; f < 128; f++) s += a[f] * w1[f * 64 + o];
        s2[m * 64 + o] = s;
    }
    __syncthreads();
    // stage 3: (8,64) @ (64,1)
    if (tid < BB) {
        const float* a = s2 + tid * 64;
        float s = b2[0];
        for (int f = 0; f < 64; f++) s += a[f] * w2[f];
        out[tid] = s;
    }
}

// ---------------- launcher ----------------
extern "C" void kernel_launch(void* const* d_in, const int* in_sizes, int n_in,
                              void* d_out, int out_size) {
    const float* x = (const float*)d_in[0];
    const float* w[5];
    const float* bs[5];
    for (int l = 0; l < 5; l++) {
        w[l] = (const float*)d_in[1 + 2 * l];
        bs[l] = (const float*)d_in[2 + 2 * l];
    }
    const float* m0w = (const float*)d_in[11];
    const float* m0b = (const float*)d_in[12];
    const float* m1w = (const float*)d_in[13];
    const float* m1b = (const float*)d_in[14];
    const float* m2w = (const float*)d_in[15];
    const float* m2b = (const float*)d_in[16];
    float* out = (float*)d_out;

    float *feat_a, *feat_b, *centerp, *dotp, *poolp;
    __nv_bfloat16 *xap, *xbp, *w12tp;
    int* idxp;
    cudaGetSymbolAddress((void**)&feat_a, g_feat_a);
    cudaGetSymbolAddress((void**)&feat_b, g_feat_b);
    cudaGetSymbolAddress((void**)&centerp, g_center);
    cudaGetSymbolAddress((void**)&dotp, g_dot);
    cudaGetSymbolAddress((void**)&poolp, g_pool);
    cudaGetSymbolAddress((void**)&xap, g_xa);
    cudaGetSymbolAddress((void**)&xbp, g_xb);
    cudaGetSymbolAddress((void**)&w12tp, g_w12t);
    cudaGetSymbolAddress((void**)&idxp, g_idx);

    const int fins[5] = {3, 64, 128, 256, 512};
    const int fouts[5] = {64, 128, 256, 512, 1024};
    float* bufs[2] = {feat_a, feat_b};
    const int M = BB * NPTS;

    const float* cur = x;
    for (int l = 0; l < 5; l++) {
        int fin = fins[l], fout = fouts[l];
        int Kp = ((3 * fin + 31) / 32) * 32;
        float* yp = dotp;
        int gx2 = (2 * fout) / 128;   // 1,2,4,8,16
        int ppb = 1024 / fout;

        convert_x<<<(M * Kp + 255) / 256, 256>>>(cur, xap, xbp, fin, Kp, M);
        convert_w12<<<(2 * fout * Kp + 255) / 256, 256>>>(w[l], w12tp, fin, fout, Kp);
        sq_kernel<<<(M + 255) / 256, 256>>>(cur, fin);

        mma_nt_sym<<<dim3(NPAIRS, 1, BB), 256>>>(xap, xbp, dotp, Kp);
        topk_kernel<<<M / 8, 256>>>(dotp);

        mma_nn_zy<<<dim3(gx2, M / 128), 256>>>(xap, w12tp, bs[l], centerp, yp, Kp, fout);

        gathermax_kernel<<<M / ppb, 256>>>(centerp, yp, idxp, bufs[l & 1], fout, ppb);
        cur = bufs[l & 1];
    }

    pool_kernel<<<dim3(MAXF / 256, BB), 256>>>(cur, MAXF);
    mlp3_kernel<<<1, 1024>>>(poolp, m0w, m0b, m1w, m1b, m2w, m2b, out);
}

// round 16
// speedup vs baseline: 2.7535x; 1.0498x over previous
#include <cuda_runtime.h>
#include <cuda_bf16.h>
#include <cstdint>

#define BB   8
#define NPTS 2048
#define KNN  10
#define MAXF 1024
#define SLOPE 0.2f
#define KPMAX 1536
#define SMPAD 40
#define NTILES 16
#define NPAIRS 136

// ---------------- static scratch ----------------
__device__ float g_feat_a[BB * NPTS * MAXF];
__device__ float g_feat_b[BB * NPTS * MAXF];
__device__ float g_center[BB * NPTS * MAXF];
__device__ float g_y[(size_t)BB * NPTS * MAXF];                          // Y (no longer aliases dot)
__device__ float g_dot[(size_t)BB * NPTS * NPTS];
__device__ __align__(16) __nv_bfloat16 g_xa[(size_t)BB * NPTS * KPMAX];  // (h,l,h)
__device__ __align__(16) __nv_bfloat16 g_xb[(size_t)BB * NPTS * KPMAX];  // (h,h,l)
__device__ __align__(16) __nv_bfloat16 g_w12t[2048 * KPMAX];             // W1^T ‖ W2^T
__device__ float g_sq[BB * NPTS];
__device__ int   g_idx[BB * NPTS * KNN];
__device__ float g_pool[BB * MAXF];

// ---------------- conversions: fp32 -> 3-slot bf16 split ----------------
__global__ void convert_x(const float* __restrict__ X, __nv_bfloat16* __restrict__ Xa,
                          __nv_bfloat16* __restrict__ Xb, int fin, int Kp, int M) {
    int idx = blockIdx.x * blockDim.x + threadIdx.x;
    if (idx >= M * Kp) return;
    int r = idx / Kp, c = idx % Kp;
    __nv_bfloat16 va = __float2bfloat16(0.f), vb = va;
    if (c < 3 * fin) {
        int s = c / fin, cc = c - s * fin;
        float v = X[(size_t)r * fin + cc];
        __nv_bfloat16 h = __float2bfloat16(v);
        __nv_bfloat16 l = __float2bfloat16(v - __bfloat162float(h));
        va = (s == 1) ? l : h;
        vb = (s == 2) ? l : h;
    }
    Xa[(size_t)r * Kp + c] = va;
    Xb[(size_t)r * Kp + c] = vb;
}

__global__ void convert_w12(const float* __restrict__ W, __nv_bfloat16* __restrict__ Wt,
                            int fin, int fout, int Kp) {
    int idx = blockIdx.x * blockDim.x + threadIdx.x;
    if (idx >= 2 * fout * Kp) return;
    int n = idx / Kp, c = idx % Kp;
    const float* src = (n < fout) ? W : W + (size_t)fin * fout;
    int nn = (n < fout) ? n : n - fout;
    __nv_bfloat16 o = __float2bfloat16(0.f);
    if (c < 3 * fin) {
        int s = c / fin, cc = c - s * fin;
        float v = src[(size_t)cc * fout + nn];
        __nv_bfloat16 h = __float2bfloat16(v);
        o = (s == 2) ? __float2bfloat16(v - __bfloat162float(h)) : h;
    }
    Wt[(size_t)n * Kp + c] = o;
}

// ---------------- MMA primitives ----------------
#define MMA_BF16(c, a, b)                                                          \
    asm volatile("mma.sync.aligned.m16n8k16.row.col.f32.bf16.bf16.f32 "            \
                 "{%0,%1,%2,%3}, {%4,%5,%6,%7}, {%8,%9}, {%0,%1,%2,%3};"           \
                 : "+f"(c[0]), "+f"(c[1]), "+f"(c[2]), "+f"(c[3])                  \
                 : "r"(a[0]), "r"(a[1]), "r"(a[2]), "r"(a[3]), "r"(b[0]), "r"(b[1]))

__device__ __forceinline__ void cpa16(void* smem, const void* gmem) {
    uint32_t s = (uint32_t)__cvta_generic_to_shared(smem);
    asm volatile("cp.async.cg.shared.global [%0], [%1], 16;" :: "r"(s), "l"(gmem));
}
__device__ __forceinline__ void ldsm_x4(uint32_t* r, const void* p) {
    uint32_t a = (uint32_t)__cvta_generic_to_shared(p);
    asm volatile("ldmatrix.sync.aligned.m8n8.x4.shared.b16 {%0,%1,%2,%3}, [%4];"
                 : "=r"(r[0]), "=r"(r[1]), "=r"(r[2]), "=r"(r[3]) : "r"(a));
}
__device__ __forceinline__ void ldsm_x2(uint32_t* r, const void* p) {
    uint32_t a = (uint32_t)__cvta_generic_to_shared(p);
    asm volatile("ldmatrix.sync.aligned.m8n8.x2.shared.b16 {%0,%1}, [%2];"
                 : "=r"(r[0]), "=r"(r[1]) : "r"(a));
}

__device__ __forceinline__ void stage_load(__nv_bfloat16 (*S)[SMPAD],
                                           const __nv_bfloat16* __restrict__ src,
                                           int row0, int Kp, int k0, int tid) {
#pragma unroll
    for (int it = 0; it < 2; it++) {
        int e = tid + it * 256;
        int r = e >> 2;
        int cb = (e & 3) * 8;
        cpa16(&S[r][cb], src + (size_t)(row0 + r) * Kp + k0 + cb);
    }
}

__device__ __forceinline__ void stage_mma(const __nv_bfloat16 (*As)[SMPAD],
                                          const __nv_bfloat16 (*Bs)[SMPAD],
                                          float acc[4][4][4], int wm, int wn, int lane) {
    int a_row = (lane & 15);
    int a_col = (lane >> 4) * 8;
    int b_row = (lane & 7);
    int b_col = ((lane >> 3) & 1) * 8;
#pragma unroll
    for (int ks = 0; ks < 2; ks++) {
        int kb = ks * 16;
        uint32_t ar[4][4], br[4][2];
#pragma unroll
        for (int mi = 0; mi < 4; mi++)
            ldsm_x4(ar[mi], &As[wm + mi * 16 + a_row][kb + a_col]);
#pragma unroll
        for (int ni = 0; ni < 4; ni++)
            ldsm_x2(br[ni], &Bs[wn + ni * 8 + b_row][kb + b_col]);
#pragma unroll
        for (int mi = 0; mi < 4; mi++)
#pragma unroll
            for (int ni = 0; ni < 4; ni++) MMA_BF16(acc[mi][ni], ar[mi], br[ni]);
    }
}

#define KLOOP3(Aptr, Bptr, m0_, n0_)                                               \
    stage_load(As[0], Aptr, m0_, Kp, 0, tid);                                      \
    stage_load(Bs[0], Bptr, n0_, Kp, 0, tid);                                      \
    asm volatile("cp.async.commit_group;");                                        \
    if (nk > 1) {                                                                  \
        stage_load(As[1], Aptr, m0_, Kp, 32, tid);                                 \
        stage_load(Bs[1], Bptr, n0_, Kp, 32, tid);                                 \
        asm volatile("cp.async.commit_group;");                                    \
    }                                                                              \
    for (int kt = 0; kt < nk; kt++) {                                              \
        if (kt + 1 < nk) asm volatile("cp.async.wait_group 1;");                   \
        else             asm volatile("cp.async.wait_group 0;");                   \
        __syncthreads();                                                           \
        if (kt + 2 < nk) {                                                         \
            int sprev = (kt + 2) % 3;                                              \
            stage_load(As[sprev], Aptr, m0_, Kp, (kt + 2) * 32, tid);              \
            stage_load(Bs[sprev], Bptr, n0_, Kp, (kt + 2) * 32, tid);              \
            asm volatile("cp.async.commit_group;");                                \
        }                                                                          \
        stage_mma(As[kt % 3], Bs[kt % 3], acc, wm, wn, lane);                      \
    }

__device__ __forceinline__ bool dless(float a, int ia, float bv, int ib) {
    return (a < bv) || (a == bv && ia < ib);
}

__device__ __forceinline__ void tk_insert(float d2, int j, float* best, int* bidx) {
    if (dless(d2, j, best[KNN - 1], bidx[KNN - 1])) {
        int m = KNN - 1;
#pragma unroll
        for (int tt = KNN - 1; tt > 0; tt--) {
            if (m == tt && dless(d2, j, best[tt - 1], bidx[tt - 1])) {
                best[tt] = best[tt - 1]; bidx[tt] = bidx[tt - 1]; m = tt - 1;
            }
        }
        best[m] = d2; bidx[m] = j;
    }
}

// ---------------- NN fused Z/Y: [Z|Y] = Xa @ [W1t|W2t]^T ----------------
__global__ __launch_bounds__(256) void mma_nn_zy(const __nv_bfloat16* __restrict__ A,
                                                 const __nv_bfloat16* __restrict__ B,
                                                 const float* __restrict__ bias,
                                                 float* __restrict__ Z,
                                                 float* __restrict__ Y,
                                                 int Kp, int fout) {
    __shared__ __align__(16) __nv_bfloat16 As[3][128][SMPAD];
    __shared__ __align__(16) __nv_bfloat16 Bs[3][128][SMPAD];
    int tid = threadIdx.x;
    int m0 = blockIdx.y * 128, o0 = blockIdx.x * 128;
    int lane = tid & 31, warp = tid >> 5;
    int wm = (warp & 1) * 64, wn = (warp >> 1) * 32;
    int nk = Kp / 32;

    float acc[4][4][4];
#pragma unroll
    for (int mi = 0; mi < 4; mi++)
#pragma unroll
        for (int ni = 0; ni < 4; ni++)
#pragma unroll
            for (int c = 0; c < 4; c++) acc[mi][ni][c] = 0.f;

    KLOOP3(A, B, m0, o0)

    int g = lane >> 2, t = lane & 3;
#pragma unroll
    for (int mi = 0; mi < 4; mi++) {
        int row = m0 + wm + mi * 16 + g;
#pragma unroll
        for (int ni = 0; ni < 4; ni++) {
            int col = o0 + wn + ni * 8 + 2 * t;
            if (col < fout) {
                float b0 = bias[col], b1 = bias[col + 1];
                *(float2*)(Z + (size_t)row * fout + col) =
                    make_float2(acc[mi][ni][0] + b0, acc[mi][ni][1] + b1);
                *(float2*)(Z + (size_t)(row + 8) * fout + col) =
                    make_float2(acc[mi][ni][2] + b0, acc[mi][ni][3] + b1);
            } else {
                int yc = col - fout;
                *(float2*)(Y + (size_t)row * fout + yc) =
                    make_float2(acc[mi][ni][0], acc[mi][ni][1]);
                *(float2*)(Y + (size_t)(row + 8) * fout + yc) =
                    make_float2(acc[mi][ni][2], acc[mi][ni][3]);
            }
        }
    }
}

// ---------------- symmetric NT: upper pairs; mirror via smem transpose ----------------
__global__ __launch_bounds__(256) void mma_nt_sym(const __nv_bfloat16* __restrict__ Xa,
                                                  const __nv_bfloat16* __restrict__ Xb,
                                                  float* __restrict__ Call, int Kp) {
    __shared__ __align__(16) __nv_bfloat16 As[3][128][SMPAD];
    __shared__ __align__(16) __nv_bfloat16 Bs[3][128][SMPAD];
    int b = blockIdx.z;
    int p = blockIdx.x;
    int ti = 0;
    while (p >= NTILES - ti) { p -= NTILES - ti; ti++; }
    int tj = ti + p;
    int m0 = ti * 128, n0 = tj * 128;

    const __nv_bfloat16* Ab = Xa + (size_t)b * NPTS * Kp;
    const __nv_bfloat16* Bb = Xb + (size_t)b * NPTS * Kp;
    float* C = Call + (size_t)b * NPTS * NPTS;
    int tid = threadIdx.x;
    int lane = tid & 31, warp = tid >> 5;
    int wm = (warp & 1) * 64, wn = (warp >> 1) * 32;
    int nk = Kp / 32;

    float acc[4][4][4];
#pragma unroll
    for (int mi = 0; mi < 4; mi++)
#pragma unroll
        for (int ni = 0; ni < 4; ni++)
#pragma unroll
            for (int c = 0; c < 4; c++) acc[mi][ni][c] = 0.f;

    KLOOP3(Ab, Bb, m0, n0)

    int g = lane >> 2, t = lane & 3;
    // upper tile store (coalesced float2 rows)
#pragma unroll
    for (int mi = 0; mi < 4; mi++) {
        int row = m0 + wm + mi * 16 + g;
#pragma unroll
        for (int ni = 0; ni < 4; ni++) {
            int col = n0 + wn + ni * 8 + 2 * t;
            *(float2*)(C + (size_t)row * NPTS + col) =
                make_float2(acc[mi][ni][0], acc[mi][ni][1]);
            *(float2*)(C + (size_t)(row + 8) * NPTS + col) =
                make_float2(acc[mi][ni][2], acc[mi][ni][3]);
        }
    }

    // mirrored lower tile: transpose through smem in 4 quarter-passes, coalesced stores
    if (ti != tj) {
        __syncthreads();               // all warps done with As stage buffers
        float (*T)[132] = (float(*)[132])(&As[0][0][0]);   // 32 x 132 fp32 = 16.9 KB
        int myq = warp >> 1;           // this warp's 32-col quarter (wn = 32*myq)
        for (int q = 0; q < 4; q++) {
            if (myq == q) {
#pragma unroll
                for (int mi = 0; mi < 4; mi++) {
                    int mr = wm + mi * 16 + g;
#pragma unroll
                    for (int ni = 0; ni < 4; ni++) {
                        int nc = ni * 8 + 2 * t;
                        T[nc][mr] = acc[mi][ni][0];
                        T[nc + 1][mr] = acc[mi][ni][1];
                        T[nc][mr + 8] = acc[mi][ni][2];
                        T[nc + 1][mr + 8] = acc[mi][ni][3];
                    }
                }
            }
            __syncthreads();
#pragma unroll
            for (int it = 0; it < 4; it++) {
                int idx = tid + it * 256;
                int r = idx >> 5, c4 = (idx & 31) * 4;
                float4 v = *(const float4*)&T[r][c4];
                *(float4*)(C + (size_t)(n0 + q * 32 + r) * NPTS + m0 + c4) = v;
            }
            __syncthreads();
        }
    }
}

// ---------------- squared norms ----------------
__global__ void sq_kernel(const float* __restrict__ X, int Kd) {
    int i = blockIdx.x * blockDim.x + threadIdx.x;
    if (i < BB * NPTS) {
        const float* p = X + (size_t)i * Kd;
        float s = 0.f;
        for (int f = 0; f < Kd; f++) s += p[f] * p[f];
        g_sq[i] = s;
    }
}

// ---------------- top-K smallest d2 per row, warp per row, float4 reads ----------------
__global__ void topk_kernel(const float* __restrict__ dotm) {
    int gwarp = (blockIdx.x * blockDim.x + threadIdx.x) >> 5;
    int lane = threadIdx.x & 31;
    if (gwarp >= BB * NPTS) return;
    int b = gwarp / NPTS, i = gwarp % NPTS;
    const float* drow = dotm + ((size_t)b * NPTS + i) * NPTS;
    const float* sqb = g_sq + b * NPTS;
    float sqi = sqb[i];

    float best[KNN];
    int bidx[KNN];
#pragma unroll
    for (int m = 0; m < KNN; m++) { best[m] = 3.0e38f; bidx[m] = 0x7fffffff; }

    for (int j0 = lane * 4; j0 < NPTS; j0 += 128) {
        float4 d = *(const float4*)(drow + j0);
        float4 s = *(const float4*)(sqb + j0);
        tk_insert(sqi + s.x - 2.0f * d.x, j0 + 0, best, bidx);
        tk_insert(sqi + s.y - 2.0f * d.y, j0 + 1, best, bidx);
        tk_insert(sqi + s.z - 2.0f * d.z, j0 + 2, best, bidx);
        tk_insert(sqi + s.w - 2.0f * d.w, j0 + 3, best, bidx);
    }

    int ptr = 0;
    for (int r = 0; r < KNN; r++) {
        float v = (ptr < KNN) ? best[ptr] : 3.0e38f;
        int jj = (ptr < KNN) ? bidx[ptr] : 0x7fffffff;
        float mv = v; int mj = jj;
#pragma unroll
        for (int off = 16; off > 0; off >>= 1) {
            float ov = __shfl_down_sync(0xffffffffu, mv, off);
            int oj = __shfl_down_sync(0xffffffffu, mj, off);
            if (dless(ov, oj, mv, mj)) { mv = ov; mj = oj; }
        }
        mv = __shfl_sync(0xffffffffu, mv, 0);
        mj = __shfl_sync(0xffffffffu, mj, 0);
        if (jj == mj && v == mv) ptr++;
        if (lane == 0) g_idx[(size_t)gwarp * KNN + r] = mj;
    }
}

// ---------------- gather-max edge conv epilogue (packed blocks) ----------------
__global__ __launch_bounds__(256) void gathermax_kernel(const float* __restrict__ Z,
                                                        const float* __restrict__ Y,
                                                        const int* __restrict__ idx,
                                                        float* __restrict__ Out,
                                                        int fout, int ppb) {
    __shared__ int nb[16 * KNN];
    int p0 = blockIdx.x * ppb;
    for (int e = threadIdx.x; e < ppb * KNN; e += blockDim.x)
        nb[e] = idx[(size_t)(p0 + e / KNN) * KNN + e % KNN];
    __syncthreads();

    int tpp = fout >> 2;
    int lp = threadIdx.x / tpp;
    int o = (threadIdx.x - lp * tpp) * 4;

    int bn = p0 + lp;
    int b = bn >> 11;
    const float* Yb = Y + (size_t)b * NPTS * fout;
    size_t base = (size_t)bn * fout;
    const int* nbp = nb + lp * KNN;

    float4 m = make_float4(-3.0e38f, -3.0e38f, -3.0e38f, -3.0e38f);
#pragma unroll
    for (int k = 0; k < KNN; k++) {
        float4 v = *(const float4*)(Yb + (size_t)nbp[k] * fout + o);
        m.x = fmaxf(m.x, v.x);
        m.y = fmaxf(m.y, v.y);
        m.z = fmaxf(m.z, v.z);
        m.w = fmaxf(m.w, v.w);
    }
    float4 z = *(const float4*)(Z + base + o);
    float4 y = *(const float4*)(Y + base + o);
    float4 h;
    h.x = z.x - y.x + m.x;
    h.y = z.y - y.y + m.y;
    h.z = z.z - y.z + m.z;
    h.w = z.w - y.w + m.w;
    h.x = (h.x > 0.f) ? h.x : SLOPE * h.x;
    h.y = (h.y > 0.f) ? h.y : SLOPE * h.y;
    h.z = (h.z > 0.f) ? h.z : SLOPE * h.z;
    h.w = (h.w > 0.f) ? h.w : SLOPE * h.w;
    *(float4*)(Out + base + o) = h;
}

// ---------------- global max pool over N ----------------
__global__ void pool_kernel(const float* __restrict__ H, int Fo) {
    int b = blockIdx.y;
    int o = blockIdx.x * blockDim.x + threadIdx.x;
    if (o < Fo) {
        float m = -3.0e38f;
        for (int n = 0; n < NPTS; n++)
            m = fmaxf(m, H[((size_t)b * NPTS + n) * Fo + o]);
        g_pool[b * Fo + o] = m;
    }
}

// ---------------- fused 3-layer MLP head ----------------
__global__ __launch_bounds__(1024) void mlp3_kernel(const float* __restrict__ A,
                                                    const float* __restrict__ w0,
                                                    const float* __restrict__ b0,
                                                    const float* __restrict__ w1,
                                                    const float* __restrict__ b1,
                                                    const float* __restrict__ w2,
                                                    const float* __restrict__ b2,
                                                    float* __restrict__ out) {
    __shared__ float s1[BB * 128];
    __shared__ float s2[BB * 64];
    int tid = threadIdx.x;
    {
        int m = tid >> 7, o = tid & 127;
        const float* a = A + m * 1024;
        float s = b0[o];
        for (int f = 0; f < 1024; f++) s += a[f] * w0[f * 128 + o];
        s1[m * 128 + o] = s;
    }
    __syncthreads();
    if (tid < BB * 64) {
        int m = tid >> 6, o = tid & 63;
        const float* a = s1 + m * 128;
        float s = b1[o];
        for (int f = 0; f < 128; f++) s += a[f] * w1[f * 64 + o];
        s2[m * 64 + o] = s;
    }
    __syncthreads();
    if (tid < BB) {
        const float* a = s2 + tid * 64;
        float s = b2[0];
        for (int f = 0; f < 64; f++) s += a[f] * w2[f];
        out[tid] = s;
    }
}

// ---------------- launcher ----------------
extern "C" void kernel_launch(void* const* d_in, const int* in_sizes, int n_in,
                              void* d_out, int out_size) {
    const float* x = (const float*)d_in[0];
    const float* w[5];
    const float* bs[5];
    for (int l = 0; l < 5; l++) {
        w[l] = (const float*)d_in[1 + 2 * l];
        bs[l] = (const float*)d_in[2 + 2 * l];
    }
    const float* m0w = (const float*)d_in[11];
    const float* m0b = (const float*)d_in[12];
    const float* m1w = (const float*)d_in[13];
    const float* m1b = (const float*)d_in[14];
    const float* m2w = (const float*)d_in[15];
    const float* m2b = (const float*)d_in[16];
    float* out = (float*)d_out;

    float *feat_a, *feat_b, *centerp, *yp, *dotp, *poolp;
    __nv_bfloat16 *xap, *xbp, *w12tp;
    int* idxp;
    cudaGetSymbolAddress((void**)&feat_a, g_feat_a);
    cudaGetSymbolAddress((void**)&feat_b, g_feat_b);
    cudaGetSymbolAddress((void**)&centerp, g_center);
    cudaGetSymbolAddress((void**)&yp, g_y);
    cudaGetSymbolAddress((void**)&dotp, g_dot);
    cudaGetSymbolAddress((void**)&poolp, g_pool);
    cudaGetSymbolAddress((void**)&xap, g_xa);
    cudaGetSymbolAddress((void**)&xbp, g_xb);
    cudaGetSymbolAddress((void**)&w12tp, g_w12t);
    cudaGetSymbolAddress((void**)&idxp, g_idx);

    // side stream + events, created once (outside graph capture: first call is eager)
    static cudaStream_t s1 = nullptr;
    static cudaEvent_t evx = nullptr, evzy = nullptr;
    if (!s1) {
        cudaStreamCreateWithFlags(&s1, cudaStreamNonBlocking);
        cudaEventCreateWithFlags(&evx, cudaEventDisableTiming);
        cudaEventCreateWithFlags(&evzy, cudaEventDisableTiming);
    }

    const int fins[5] = {3, 64, 128, 256, 512};
    const int fouts[5] = {64, 128, 256, 512, 1024};
    float* bufs[2] = {feat_a, feat_b};
    const int M = BB * NPTS;

    const float* cur = x;
    for (int l = 0; l < 5; l++) {
        int fin = fins[l], fout = fouts[l];
        int Kp = ((3 * fin + 31) / 32) * 32;
        int gx2 = (2 * fout) / 128;
        int ppb = 1024 / fout;

        // main stream: feature split (both chains depend on it)
        convert_x<<<(M * Kp + 255) / 256, 256>>>(cur, xap, xbp, fin, Kp, M);
        cudaEventRecord(evx, 0);

        // side stream: weight split + fused Z/Y GEMM (independent of kNN chain)
        cudaStreamWaitEvent(s1, evx, 0);
        convert_w12<<<(2 * fout * Kp + 255) / 256, 256, 0, s1>>>(w[l], w12tp, fin, fout, Kp);
        mma_nn_zy<<<dim3(gx2, M / 128), 256, 0, s1>>>(xap, w12tp, bs[l], centerp, yp, Kp, fout);
        cudaEventRecord(evzy, s1);

        // main stream: kNN chain
        sq_kernel<<<(M + 255) / 256, 256>>>(cur, fin);
        mma_nt_sym<<<dim3(NPAIRS, 1, BB), 256>>>(xap, xbp, dotp, Kp);
        topk_kernel<<<M / 8, 256>>>(dotp);

        // join: gathermax needs Z, Y (side) and idx (main)
        cudaStreamWaitEvent(0, evzy, 0);
        gathermax_kernel<<<M / ppb, 256>>>(centerp, yp, idxp, bufs[l & 1], fout, ppb);
        cur = bufs[l & 1];
    }

    pool_kernel<<<dim3(MAXF / 256, BB), 256>>>(cur, MAXF);
    mlp3_kernel<<<1, 1024>>>(poolp, m0w, m0b, m1w, m1b, m2w, m2b, out);
}